// round 9
// baseline (speedup 1.0000x reference)
#include <cuda_runtime.h>
#include <cuda_bf16.h>
#include <math_constants.h>
#include <cstdint>

// ---------------- problem constants ----------------
constexpr int C_  = 64;
constexpr int L_  = 720;
constexpr int P_  = 336;
constexpr int P2_ = 168;
constexpr int M_  = 4096;   // B*C
constexpr int KPX = 768;    // 720 padded to 64

// ---------------- weight pool offsets (transposed [Nall][Kpad] bf16) -----
constexpr size_t OFF_WH  = 0;                 constexpr size_t SZ_WH  = 512  * 768;
constexpr size_t OFF_SSZ = OFF_WH  + SZ_WH;   constexpr size_t SZ_SSZ = 1024 * 512;
constexpr size_t OFF_XZ2 = OFF_SSZ + SZ_SSZ;  constexpr size_t SZ_XZ  = 1024 * 768;
constexpr size_t OFF_XZ3 = OFF_XZ2 + SZ_XZ;
constexpr size_t OFF_XZ4 = OFF_XZ3 + SZ_XZ;
constexpr size_t OFF_XZ5 = OFF_XZ4 + SZ_XZ;
constexpr size_t OFF_ZX0 = OFF_XZ5 + SZ_XZ;   constexpr size_t SZ_ZX  = 1440 * 512;
constexpr size_t OFF_ZX2 = OFF_ZX0 + SZ_ZX;
constexpr size_t OFF_ZX3 = OFF_ZX2 + SZ_ZX;
constexpr size_t OFF_ZY  = OFF_ZX3 + SZ_ZX;   constexpr size_t SZ_ZY  = 672 * 512;
constexpr size_t OFF_ROT = OFF_ZY  + SZ_ZY;   constexpr size_t SZ_ROT = 168 * 512;
constexpr size_t OFF_KOO = OFF_ROT + SZ_ROT;  constexpr size_t SZ_KOO = 672 * 512;
constexpr size_t POOL    = OFF_KOO + SZ_KOO;

// ---------------- static device scratch ----------------
__device__ __align__(128) __nv_bfloat16 g_wph[POOL];
__device__ __align__(128) __nv_bfloat16 g_wpl[POOL];
__device__ __align__(128) __nv_bfloat16 g_xh[M_ * KPX], g_xl[M_ * KPX];
__device__ __align__(128) __nv_bfloat16 g_hh[M_ * 512], g_hl[M_ * 512];
__device__ __align__(128) __nv_bfloat16 g_zh[M_ * 512], g_zl[M_ * 512];
__device__ __align__(128) float g_y [M_ * P_];
__device__ __align__(128) float g_th[M_ * P2_];

// ---------------- helpers ----------------
__device__ __forceinline__ uint32_t smem_u32(const void* p) {
    uint32_t a;
    asm("{ .reg .u64 t; cvta.to.shared.u64 t, %1; cvt.u32.u64 %0, t; }" : "=r"(a) : "l"(p));
    return a;
}
__device__ __forceinline__ uint32_t swz(uint32_t o) { return o ^ ((o >> 3) & 0x70); }

__device__ __forceinline__ void cp16(uint32_t dst, const void* src) {
    asm volatile("cp.async.cg.shared.global [%0], [%1], 16;" :: "r"(dst), "l"(src));
}
__device__ __forceinline__ void cp16z(uint32_t dst, const void* src, uint32_t sz) {
    asm volatile("cp.async.cg.shared.global [%0], [%1], 16, %2;"
                 :: "r"(dst), "l"(src), "r"(sz));
}
__device__ __forceinline__ void cp_commit() {
    asm volatile("cp.async.commit_group;" ::: "memory");
}
template <int N>
__device__ __forceinline__ void cp_wait() {
    asm volatile("cp.async.wait_group %0;" :: "n"(N) : "memory");
}
__device__ __forceinline__ void ldsm4(uint32_t* r, uint32_t a) {
    asm volatile("ldmatrix.sync.aligned.m8n8.x4.shared.b16 {%0,%1,%2,%3}, [%4];"
                 : "=r"(r[0]), "=r"(r[1]), "=r"(r[2]), "=r"(r[3]) : "r"(a));
}
__device__ __forceinline__ void mma_bf16(float* d, const uint32_t* a, const uint32_t* b) {
    asm volatile(
        "mma.sync.aligned.m16n8k16.row.col.f32.bf16.bf16.f32 "
        "{%0,%1,%2,%3}, {%4,%5,%6,%7}, {%8,%9}, {%0,%1,%2,%3};"
        : "+f"(d[0]), "+f"(d[1]), "+f"(d[2]), "+f"(d[3])
        : "r"(a[0]), "r"(a[1]), "r"(a[2]), "r"(a[3]), "r"(b[0]), "r"(b[1]));
}
__device__ __forceinline__ float gelu_tanh(float x) {
    float x3 = x * x * x;
    return 0.5f * x * (1.0f + tanhf(0.7978845608028654f * (x + 0.044715f * x3)));
}
__device__ __forceinline__ void split_bf(float v, __nv_bfloat16& h, __nv_bfloat16& l) {
    h = __float2bfloat16(v);
    l = __float2bfloat16(v - __bfloat162float(h));
}

// ---------------- merged prep: all 12 weights in one kernel --------------
struct ConvAll {
    const float* src[12];
    __nv_bfloat16* hi[12];
    __nv_bfloat16* lo[12];
    int K[12], Nall[12], Kpad[12];
    int base[13];
};

__global__ void convert_all(ConvAll a)
{
    __shared__ float t[32][33];
    int bid = blockIdx.x;
    int w = 0;
    while (bid >= a.base[w + 1]) ++w;
    int local = bid - a.base[w];
    const int K = a.K[w], Nall = a.Nall[w], Kpad = a.Kpad[w];
    const int tilesY = (Nall + 31) >> 5;
    const int k0 = (local / tilesY) * 32, n0 = (local % tilesY) * 32;
    const float* W = a.src[w];
    __nv_bfloat16* Hi = a.hi[w];
    __nv_bfloat16* Lo = a.lo[w];

    for (int i = threadIdx.y; i < 32; i += 8) {
        int k = k0 + i, n = n0 + threadIdx.x;
        t[i][threadIdx.x] = (k < K && n < Nall) ? W[(size_t)k * Nall + n] : 0.f;
    }
    __syncthreads();
    for (int i = threadIdx.y; i < 32; i += 8) {
        int n = n0 + i, k = k0 + threadIdx.x;
        if (n < Nall && k < Kpad) {
            __nv_bfloat16 h, l; split_bf(t[threadIdx.x][i], h, l);
            Hi[(size_t)n * Kpad + k] = h;
            Lo[(size_t)n * Kpad + k] = l;
        }
    }
}

// ---------------- prep: x_bsd [64][720][64] -> xT hi/lo [4096][768] ------
__global__ void convert_x(const float* __restrict__ X,
                          __nv_bfloat16* __restrict__ Hi, __nv_bfloat16* __restrict__ Lo)
{
    __shared__ float t[32][33];
    int l0 = blockIdx.x * 32, c0 = blockIdx.y * 32, b = blockIdx.z;
    for (int i = threadIdx.y; i < 32; i += 8) {
        int l = l0 + i;
        t[i][threadIdx.x] = (l < L_) ? X[((size_t)b * L_ + l) * C_ + c0 + threadIdx.x] : 0.f;
    }
    __syncthreads();
    for (int i = threadIdx.y; i < 32; i += 8) {
        int c = c0 + i, l = l0 + threadIdx.x;
        __nv_bfloat16 h, lo; split_bf(t[threadIdx.x][i], h, lo);
        size_t o = (size_t)(b * 64 + c) * KPX + l;
        Hi[o] = h; Lo[o] = lo;
    }
}

// -- fused mma.sync GEMM: 128x256 tile, 8 warps (64x64), k32 double-buffer --
// For PAIR epilogues B rows are interleaved: tile row 2j = s-col j, 2j+1 = t-col j.
enum { EP_GELU = 0, EP_TANHPI = 1, EP_AFF = 2, EP_FINAL = 3 };

template <int EPI>
__global__ __launch_bounds__(256)
void gemm_mma(const __nv_bfloat16* __restrict__ AH, const __nv_bfloat16* __restrict__ AL,
              int ldA, int KC32,
              const __nv_bfloat16* __restrict__ WH, const __nv_bfloat16* __restrict__ WL,
              int ldW, int Nlog,
              const float* __restrict__ VinF,
              const __nv_bfloat16* __restrict__ VinH, const __nv_bfloat16* __restrict__ VinL,
              int ldV, float vscale,
              const float* __restrict__ Theta,
              const float* __restrict__ Ay, const float* __restrict__ By,
              __nv_bfloat16* __restrict__ OutH, __nv_bfloat16* __restrict__ OutL,
              float* __restrict__ OutF, int ldO)
{
    constexpr bool PAIR = (EPI == EP_AFF || EPI == EP_FINAL);

    extern __shared__ __align__(16) char smraw[];
    const uint32_t sbRaw = smem_u32(smraw);
    const uint32_t abU   = (sbRaw + 1023u) & ~1023u;
    char* ab = smraw + (abU - sbRaw);

    const int tid = threadIdx.x, wid = tid >> 5, lane = tid & 31;
    const int m0 = blockIdx.x * 128;
    const int n0 = blockIdx.y * (PAIR ? 128 : 256);   // logical cols per CTA

    const int wm = wid >> 2, wn = wid & 3;   // 2 x 4 warp grid, 64x64 tiles
    float acc[4][8][4];
#pragma unroll
    for (int a = 0; a < 4; ++a)
#pragma unroll
        for (int b = 0; b < 8; ++b)
#pragma unroll
            for (int c = 0; c < 4; ++c) acc[a][b][c] = 0.f;

    // smem: Ah 16K | Al 16K | Bh 32K | Bl 32K  (128B rows = k64 as two k32 halves)
    const uint32_t uA = abU, uAl = abU + 16384, uB = abU + 32768, uBl = abU + 65536;

    const uint32_t aoffb = (uint32_t)(wm * 64 + (lane & 15)) * 128;
    const uint32_t boffb = (uint32_t)(wn * 64 + ((lane >> 4) & 1) * 8 + (lane & 7)) * 128;
    const uint32_t lx  = (lane & 7) * 16;
    const uint32_t acb = ((lane >> 4) & 1) * 16;
    const uint32_t bcb = ((lane >> 3) & 1) * 16;

    // ---- chunk loader: k32 chunk c -> half (c&1) of the 128B rows ----
    auto issue_chunk = [&](int c) {
        const uint32_t hb = (uint32_t)(c & 1) * 64;
#pragma unroll
        for (int i = 0; i < 2; ++i) {          // A: 128 rows x 4 q
            int idx = tid + i * 256;
            int r = idx >> 2, q = idx & 3;
            uint32_t so = swz((uint32_t)(r * 128) + hb + q * 16);
            size_t go = (size_t)(m0 + r) * ldA + c * 32 + q * 8;
            cp16(uA  + so, AH + go);
            cp16(uAl + so, AL + go);
        }
#pragma unroll
        for (int i = 0; i < 4; ++i) {          // B: 256 rows x 4 q
            int idx = tid + i * 256;
            int r = idx >> 2, q = idx & 3;
            int wr, ok;
            if (PAIR) {
                int j = n0 + (r >> 1);
                ok = j < Nlog;
                wr = (r & 1) ? (Nlog + j) : j;
            } else { wr = n0 + r; ok = wr < Nlog; }
            int wrc = ok ? wr : 0;
            uint32_t sz = ok ? 16u : 0u;
            uint32_t so = swz((uint32_t)(r * 128) + hb + q * 16);
            size_t go = (size_t)wrc * ldW + c * 32 + q * 8;
            cp16z(uB  + so, WH + go, sz);
            cp16z(uBl + so, WL + go, sz);
        }
        cp_commit();
    };

    // ---- compute one k32 chunk ----
    auto compute = [&](int c) {
        const uint32_t hb = (uint32_t)(c & 1) * 64;
#pragma unroll
        for (int ks = 0; ks < 2; ++ks) {
            const uint32_t kb = hb + ks * 32;
            const uint32_t axor = (kb + acb) ^ lx;
            const uint32_t bxor = (kb + bcb) ^ lx;
            uint32_t ah[4][4], al[4][4], bh[4][4], bl[4][4];
#pragma unroll
            for (int t = 0; t < 4; ++t) ldsm4(ah[t], uA + aoffb + t * 2048 + axor);
#pragma unroll
            for (int t = 0; t < 4; ++t) ldsm4(bh[t], uB + boffb + t * 2048 + bxor);
#pragma unroll
            for (int mt = 0; mt < 4; ++mt)
#pragma unroll
                for (int nt = 0; nt < 8; ++nt)
                    mma_bf16(acc[mt][nt], ah[mt], &bh[nt >> 1][(nt & 1) * 2]);
#pragma unroll
            for (int t = 0; t < 4; ++t) ldsm4(bl[t], uBl + boffb + t * 2048 + bxor);
#pragma unroll
            for (int mt = 0; mt < 4; ++mt)
#pragma unroll
                for (int nt = 0; nt < 8; ++nt)
                    mma_bf16(acc[mt][nt], ah[mt], &bl[nt >> 1][(nt & 1) * 2]);
#pragma unroll
            for (int t = 0; t < 4; ++t) ldsm4(al[t], uAl + aoffb + t * 2048 + axor);
#pragma unroll
            for (int mt = 0; mt < 4; ++mt)
#pragma unroll
                for (int nt = 0; nt < 8; ++nt)
                    mma_bf16(acc[mt][nt], al[mt], &bh[nt >> 1][(nt & 1) * 2]);
        }
    };

    // ---- k32 double-buffered mainloop ----
    issue_chunk(0);
    if (KC32 > 1) issue_chunk(1);
#pragma unroll 1
    for (int c = 0; c < KC32; ++c) {
        if (c + 1 < KC32) cp_wait<1>(); else cp_wait<0>();
        __syncthreads();
        compute(c);
        __syncthreads();
        if (c + 2 < KC32) issue_chunk(c + 2);
    }

    // ---- epilogue: 2 passes of 128 smem cols (aliases stage memory) ----
    constexpr int PITCH = 132;
    float* sAcc = reinterpret_cast<float*>(ab);

#pragma unroll 1
    for (int pass = 0; pass < 2; ++pass) {
        __syncthreads();
        if ((wn >> 1) == pass) {
            const int tr = lane >> 2, tc = (lane & 3) * 2;
#pragma unroll
            for (int mt = 0; mt < 4; ++mt)
#pragma unroll
                for (int nt = 0; nt < 8; ++nt) {
                    int row = wm * 64 + mt * 16 + tr;
                    int col = (wn & 1) * 64 + nt * 8 + tc;
                    *reinterpret_cast<float2*>(&sAcc[row * PITCH + col]) =
                        make_float2(acc[mt][nt][0], acc[mt][nt][1]);
                    *reinterpret_cast<float2*>(&sAcc[(row + 8) * PITCH + col]) =
                        make_float2(acc[mt][nt][2], acc[mt][nt][3]);
                }
        }
        __syncthreads();

        if (EPI == EP_GELU || EPI == EP_TANHPI) {
            for (int r = wid; r < 128; r += 8) {
                size_t ro = (size_t)(m0 + r) * ldO;
                for (int c = lane; c < 128; c += 32) {
                    int n = n0 + pass * 128 + c;
                    if (n >= Nlog) break;
                    float a0 = sAcc[r * PITCH + c];
                    float v = (EPI == EP_GELU) ? gelu_tanh(a0) : CUDART_PI_F * tanhf(a0);
                    if (OutF) OutF[ro + n] = v;
                    else { __nv_bfloat16 h, l; split_bf(v, h, l);
                           OutH[ro + n] = h; OutL[ro + n] = l; }
                }
            }
        } else if (EPI == EP_AFF) {
            for (int r = wid; r < 128; r += 8) {
                size_t rv = (size_t)(m0 + r) * ldV, ro = (size_t)(m0 + r) * ldO;
                for (int u = lane; u < 64; u += 32) {
                    int n = n0 + pass * 64 + u;
                    if (n >= Nlog) break;
                    float2 st = *reinterpret_cast<float2*>(&sAcc[r * PITCH + 2 * u]);
                    float vin = VinF ? VinF[rv + n] * vscale
                                     : __bfloat162float(VinH[rv + n]) +
                                       __bfloat162float(VinL[rv + n]);
                    float v = vin * __expf(tanhf(st.x)) + st.y;
                    if (OutF) OutF[ro + n] = v;
                    else { __nv_bfloat16 h, l; split_bf(v, h, l);
                           OutH[ro + n] = h; OutL[ro + n] = l; }
                }
            }
        } else { // EP_FINAL: lane handles one complex pair (cols n, n+1)
            for (int r = wid; r < 128; r += 8) {
                int gm = m0 + r, cch = gm & 63, bb = gm >> 6;
                size_t rv = (size_t)gm * ldV;
                int n = n0 + pass * 64 + 2 * lane;
                if (n >= Nlog) continue;
                int p = n >> 1;
                float4 st = *reinterpret_cast<float4*>(&sAcc[r * PITCH + 4 * lane]);
                // st = (s_n, t_n, s_{n+1}, t_{n+1})
                float th = Theta[(size_t)gm * P2_ + p], sn, cs;
                sincosf(th, &sn, &cs);
                float av = Ay[cch * P2_ + p], bv = By[cch * P2_ + p];
                float rn = rsqrtf(av * av + bv * bv);
                float ca = av * rn, cb = bv * rn;
                float2 yv = *reinterpret_cast<const float2*>(VinF + rv + n);
                float r1 = cs * yv.x - sn * yv.y, i1 = sn * yv.x + cs * yv.y;
                float r2 = ca * r1 - cb * i1, i2 = cb * r1 + ca * i1;
                float r3 = r2 * __expf(tanhf(st.x)), i3 = i2 * __expf(tanhf(st.z));
                float r4 = ca * r3 + cb * i3,  i4 = -cb * r3 + ca * i3;
                float r5 = cs * r4 + sn * i4,  i5 = -sn * r4 + cs * i4;
                OutF[((size_t)bb * P_ + n) * C_ + cch]     = r5 + st.y;
                OutF[((size_t)bb * P_ + n + 1) * C_ + cch] = i5 + st.w;
            }
        }
    }
}

// ---------------- host ----------------
constexpr int SMEMSZ = 98304 + 1024;

extern "C" void kernel_launch(void* const* d_in, const int* in_sizes, int n_in,
                              void* d_out, int out_size)
{
    (void)in_sizes; (void)n_in; (void)out_size;
    const float* x_bsd = (const float*)d_in[0];
    const float* z0    = (const float*)d_in[1];
    const float* y0    = (const float*)d_in[2];
    const float* a_y   = (const float*)d_in[16];
    const float* b_y   = (const float*)d_in[17];
    float* out = (float*)d_out;

    __nv_bfloat16 *wph, *wpl, *xh, *xl, *hh, *hl, *zh, *zl;
    float *y, *th;
    cudaGetSymbolAddress((void**)&wph, g_wph);
    cudaGetSymbolAddress((void**)&wpl, g_wpl);
    cudaGetSymbolAddress((void**)&xh, g_xh);  cudaGetSymbolAddress((void**)&xl, g_xl);
    cudaGetSymbolAddress((void**)&hh, g_hh);  cudaGetSymbolAddress((void**)&hl, g_hl);
    cudaGetSymbolAddress((void**)&zh, g_zh);  cudaGetSymbolAddress((void**)&zl, g_zl);
    cudaGetSymbolAddress((void**)&y,  g_y);   cudaGetSymbolAddress((void**)&th, g_th);

    static bool attr_done = false;
    if (!attr_done) {
        cudaFuncSetAttribute(gemm_mma<EP_GELU>,   cudaFuncAttributeMaxDynamicSharedMemorySize, SMEMSZ);
        cudaFuncSetAttribute(gemm_mma<EP_TANHPI>, cudaFuncAttributeMaxDynamicSharedMemorySize, SMEMSZ);
        cudaFuncSetAttribute(gemm_mma<EP_AFF>,    cudaFuncAttributeMaxDynamicSharedMemorySize, SMEMSZ);
        cudaFuncSetAttribute(gemm_mma<EP_FINAL>,  cudaFuncAttributeMaxDynamicSharedMemorySize, SMEMSZ);
        attr_done = true;
    }

    // ---- merged weight conversion ----
    struct WS { int idx; int K, Nall, Kpad; size_t off; };
    const WS ws[12] = {
        {3, 720, 512, 768, OFF_WH},  {4, 512, 1024, 512, OFF_SSZ},
        {5, 720, 1024, 768, OFF_XZ2},{6, 720, 1024, 768, OFF_XZ3},
        {7, 720, 1024, 768, OFF_XZ4},{8, 720, 1024, 768, OFF_XZ5},
        {9, 512, 1440, 512, OFF_ZX0},{10,512, 1440, 512, OFF_ZX2},
        {11,512, 1440, 512, OFF_ZX3},{13,512, 672,  512, OFF_ZY},
        {14,512, 168,  512, OFF_ROT},{15,512, 672,  512, OFF_KOO},
    };
    ConvAll ca;
    int total = 0;
    for (int i = 0; i < 12; ++i) {
        ca.src[i]  = (const float*)d_in[ws[i].idx];
        ca.hi[i]   = wph + ws[i].off;
        ca.lo[i]   = wpl + ws[i].off;
        ca.K[i]    = ws[i].K;
        ca.Nall[i] = ws[i].Nall;
        ca.Kpad[i] = ws[i].Kpad;
        ca.base[i] = total;
        total += (ws[i].Kpad / 32) * ((ws[i].Nall + 31) / 32);
    }
    ca.base[12] = total;
    convert_all<<<total, dim3(32, 8)>>>(ca);
    convert_x<<<dim3(24, 2, 64), dim3(32, 8)>>>(x_bsd, xh, xl);

    const __nv_bfloat16* Z = nullptr; const float* ZF = nullptr;

    // ---- GEMM chain (W_zx_v5 branch dead in reference: skipped) ----
    // h = gelu(xT @ W_h)                       K=736 chunks=23
    gemm_mma<EP_GELU><<<dim3(32, 2), 256, SMEMSZ>>>(
        xh, xl, 768, 23, wph + OFF_WH, wpl + OFF_WH, 768, 512,
        ZF, Z, Z, 0, 0.f, ZF, ZF, ZF, hh, hl, nullptr, 512);
    // z = affine(0.1*z0 ; h @ W_ssz)
    gemm_mma<EP_AFF><<<dim3(32, 4), 256, SMEMSZ>>>(
        hh, hl, 512, 16, wph + OFF_SSZ, wpl + OFF_SSZ, 512, 512,
        z0, Z, Z, 512, 0.1f, ZF, ZF, ZF, zh, zl, nullptr, 512);
    // x = affine(xT ; z @ W_zx_v0)
    gemm_mma<EP_AFF><<<dim3(32, 6), 256, SMEMSZ>>>(
        zh, zl, 512, 16, wph + OFF_ZX0, wpl + OFF_ZX0, 512, 720,
        ZF, xh, xl, 768, 1.f, ZF, ZF, ZF, xh, xl, nullptr, 768);
    // z = affine(z ; x @ W_xz_v2)
    gemm_mma<EP_AFF><<<dim3(32, 4), 256, SMEMSZ>>>(
        xh, xl, 768, 23, wph + OFF_XZ2, wpl + OFF_XZ2, 768, 512,
        ZF, zh, zl, 512, 1.f, ZF, ZF, ZF, zh, zl, nullptr, 512);
    // x = affine(x ; z @ W_zx_v2)
    gemm_mma<EP_AFF><<<dim3(32, 6), 256, SMEMSZ>>>(
        zh, zl, 512, 16, wph + OFF_ZX2, wpl + OFF_ZX2, 512, 720,
        ZF, xh, xl, 768, 1.f, ZF, ZF, ZF, xh, xl, nullptr, 768);
    // z = affine(z ; x @ W_xz_v3)
    gemm_mma<EP_AFF><<<dim3(32, 4), 256, SMEMSZ>>>(
        xh, xl, 768, 23, wph + OFF_XZ3, wpl + OFF_XZ3, 768, 512,
        ZF, zh, zl, 512, 1.f, ZF, ZF, ZF, zh, zl, nullptr, 512);
    // x = affine(x ; z @ W_zx_v3)
    gemm_mma<EP_AFF><<<dim3(32, 6), 256, SMEMSZ>>>(
        zh, zl, 512, 16, wph + OFF_ZX3, wpl + OFF_ZX3, 512, 720,
        ZF, xh, xl, 768, 1.f, ZF, ZF, ZF, xh, xl, nullptr, 768);
    // z = affine(z ; x @ W_xz_v4)
    gemm_mma<EP_AFF><<<dim3(32, 4), 256, SMEMSZ>>>(
        xh, xl, 768, 23, wph + OFF_XZ4, wpl + OFF_XZ4, 768, 512,
        ZF, zh, zl, 512, 1.f, ZF, ZF, ZF, zh, zl, nullptr, 512);
    // y = affine(0.1*y0 ; z @ W_zy_v4)   (f32 out)
    gemm_mma<EP_AFF><<<dim3(32, 3), 256, SMEMSZ>>>(
        zh, zl, 512, 16, wph + OFF_ZY, wpl + OFF_ZY, 512, 336,
        y0, Z, Z, 336, 0.1f, ZF, ZF, ZF, nullptr, nullptr, y, 336);
    // z = affine(z ; x @ W_xz_v5)
    gemm_mma<EP_AFF><<<dim3(32, 4), 256, SMEMSZ>>>(
        xh, xl, 768, 23, wph + OFF_XZ5, wpl + OFF_XZ5, 768, 512,
        ZF, zh, zl, 512, 1.f, ZF, ZF, ZF, zh, zl, nullptr, 512);
    // theta = pi*tanh(z @ W_rot)         (f32 out)
    gemm_mma<EP_TANHPI><<<dim3(32, 1), 256, SMEMSZ>>>(
        zh, zl, 512, 16, wph + OFF_ROT, wpl + OFF_ROT, 512, 168,
        ZF, Z, Z, 0, 0.f, ZF, ZF, ZF, nullptr, nullptr, th, 168);
    // final: z @ W_koo -> scale/shift + rot/koop chain, transposed store
    gemm_mma<EP_FINAL><<<dim3(32, 3), 256, SMEMSZ>>>(
        zh, zl, 512, 16, wph + OFF_KOO, wpl + OFF_KOO, 512, 336,
        y, Z, Z, 336, 1.f, th, a_y, b_y, nullptr, nullptr, out, 0);
}

// round 10
// speedup vs baseline: 1.3776x; 1.3776x over previous
#include <cuda_runtime.h>
#include <cuda_bf16.h>
#include <math_constants.h>
#include <cstdint>

// ---------------- problem constants ----------------
constexpr int C_  = 64;
constexpr int L_  = 720;
constexpr int P_  = 336;
constexpr int P2_ = 168;
constexpr int M_  = 4096;   // B*C
constexpr int KPX = 768;    // 720 padded to 64

// ---------------- weight pool offsets (transposed [Nall][Kpad] bf16) -----
constexpr size_t OFF_WH  = 0;                 constexpr size_t SZ_WH  = 512  * 768;
constexpr size_t OFF_SSZ = OFF_WH  + SZ_WH;   constexpr size_t SZ_SSZ = 1024 * 512;
constexpr size_t OFF_XZ2 = OFF_SSZ + SZ_SSZ;  constexpr size_t SZ_XZ  = 1024 * 768;
constexpr size_t OFF_XZ3 = OFF_XZ2 + SZ_XZ;
constexpr size_t OFF_XZ4 = OFF_XZ3 + SZ_XZ;
constexpr size_t OFF_XZ5 = OFF_XZ4 + SZ_XZ;
constexpr size_t OFF_ZX0 = OFF_XZ5 + SZ_XZ;   constexpr size_t SZ_ZX  = 1440 * 512;
constexpr size_t OFF_ZX2 = OFF_ZX0 + SZ_ZX;
constexpr size_t OFF_ZX3 = OFF_ZX2 + SZ_ZX;
constexpr size_t OFF_ZY  = OFF_ZX3 + SZ_ZX;   constexpr size_t SZ_ZY  = 672 * 512;
constexpr size_t OFF_ROT = OFF_ZY  + SZ_ZY;   constexpr size_t SZ_ROT = 168 * 512;
constexpr size_t OFF_KOO = OFF_ROT + SZ_ROT;  constexpr size_t SZ_KOO = 672 * 512;
constexpr size_t POOL    = OFF_KOO + SZ_KOO;

// ---------------- static device scratch ----------------
__device__ __align__(128) __nv_bfloat16 g_wph[POOL];
__device__ __align__(128) __nv_bfloat16 g_wpl[POOL];
__device__ __align__(128) __nv_bfloat16 g_xh[M_ * KPX], g_xl[M_ * KPX];
__device__ __align__(128) __nv_bfloat16 g_hh[M_ * 512], g_hl[M_ * 512];
__device__ __align__(128) __nv_bfloat16 g_zh[M_ * 512], g_zl[M_ * 512];
__device__ __align__(128) float g_y [M_ * P_];
__device__ __align__(128) float g_th[M_ * P2_];

// ---------------- helpers ----------------
__device__ __forceinline__ uint32_t smem_u32(const void* p) {
    uint32_t a;
    asm("{ .reg .u64 t; cvta.to.shared.u64 t, %1; cvt.u32.u64 %0, t; }" : "=r"(a) : "l"(p));
    return a;
}
__device__ __forceinline__ void cp16(uint32_t dst, const void* src) {
    asm volatile("cp.async.cg.shared.global [%0], [%1], 16;" :: "r"(dst), "l"(src));
}
__device__ __forceinline__ void cp16z(uint32_t dst, const void* src, uint32_t sz) {
    asm volatile("cp.async.cg.shared.global [%0], [%1], 16, %2;"
                 :: "r"(dst), "l"(src), "r"(sz));
}
__device__ __forceinline__ void cp_commit() {
    asm volatile("cp.async.commit_group;" ::: "memory");
}
template <int N>
__device__ __forceinline__ void cp_wait() {
    asm volatile("cp.async.wait_group %0;" :: "n"(N) : "memory");
}
__device__ __forceinline__ void ldsm4(uint32_t* r, uint32_t a) {
    asm volatile("ldmatrix.sync.aligned.m8n8.x4.shared.b16 {%0,%1,%2,%3}, [%4];"
                 : "=r"(r[0]), "=r"(r[1]), "=r"(r[2]), "=r"(r[3]) : "r"(a));
}
__device__ __forceinline__ void mma_bf16(float* d, const uint32_t* a, const uint32_t* b) {
    asm volatile(
        "mma.sync.aligned.m16n8k16.row.col.f32.bf16.bf16.f32 "
        "{%0,%1,%2,%3}, {%4,%5,%6,%7}, {%8,%9}, {%0,%1,%2,%3};"
        : "+f"(d[0]), "+f"(d[1]), "+f"(d[2]), "+f"(d[3])
        : "r"(a[0]), "r"(a[1]), "r"(a[2]), "r"(a[3]), "r"(b[0]), "r"(b[1]));
}
__device__ __forceinline__ float gelu_tanh(float x) {
    float x3 = x * x * x;
    return 0.5f * x * (1.0f + tanhf(0.7978845608028654f * (x + 0.044715f * x3)));
}
__device__ __forceinline__ void split_bf(float v, __nv_bfloat16& h, __nv_bfloat16& l) {
    h = __float2bfloat16(v);
    l = __float2bfloat16(v - __bfloat162float(h));
}

// ---------------- merged prep: all 12 weights in one kernel --------------
struct ConvAll {
    const float* src[12];
    __nv_bfloat16* hi[12];
    __nv_bfloat16* lo[12];
    int K[12], Nall[12], Kpad[12];
    int base[13];
};

__global__ void convert_all(ConvAll a)
{
    __shared__ float t[32][33];
    int bid = blockIdx.x;
    int w = 0;
    while (bid >= a.base[w + 1]) ++w;
    int local = bid - a.base[w];
    const int K = a.K[w], Nall = a.Nall[w], Kpad = a.Kpad[w];
    const int tilesY = (Nall + 31) >> 5;
    const int k0 = (local / tilesY) * 32, n0 = (local % tilesY) * 32;
    const float* W = a.src[w];
    __nv_bfloat16* Hi = a.hi[w];
    __nv_bfloat16* Lo = a.lo[w];

    for (int i = threadIdx.y; i < 32; i += 8) {
        int k = k0 + i, n = n0 + threadIdx.x;
        t[i][threadIdx.x] = (k < K && n < Nall) ? W[(size_t)k * Nall + n] : 0.f;
    }
    __syncthreads();
    for (int i = threadIdx.y; i < 32; i += 8) {
        int n = n0 + i, k = k0 + threadIdx.x;
        if (n < Nall && k < Kpad) {
            __nv_bfloat16 h, l; split_bf(t[threadIdx.x][i], h, l);
            Hi[(size_t)n * Kpad + k] = h;
            Lo[(size_t)n * Kpad + k] = l;
        }
    }
}

// ---------------- prep: x_bsd [64][720][64] -> xT hi/lo [4096][768] ------
__global__ void convert_x(const float* __restrict__ X,
                          __nv_bfloat16* __restrict__ Hi, __nv_bfloat16* __restrict__ Lo)
{
    __shared__ float t[32][33];
    int l0 = blockIdx.x * 32, c0 = blockIdx.y * 32, b = blockIdx.z;
    for (int i = threadIdx.y; i < 32; i += 8) {
        int l = l0 + i;
        t[i][threadIdx.x] = (l < L_) ? X[((size_t)b * L_ + l) * C_ + c0 + threadIdx.x] : 0.f;
    }
    __syncthreads();
    for (int i = threadIdx.y; i < 32; i += 8) {
        int c = c0 + i, l = l0 + threadIdx.x;
        __nv_bfloat16 h, lo; split_bf(t[threadIdx.x][i], h, lo);
        size_t o = (size_t)(b * 64 + c) * KPX + l;
        Hi[o] = h; Lo[o] = lo;
    }
}

// -- fused mma.sync GEMM: 128x128 tile, 8 warps, 3-deep k32 pipeline ------
// Chunk buffer (32KB): Ah 8K | Al 8K | Bh 8K | Bl 8K.  Rows (64B of k32)
// are packed two-per-128B-line: line = r&63, half = r>>6; SW128 swizzled.
enum { EP_GELU = 0, EP_TANHPI = 1, EP_AFF = 2, EP_FINAL = 3 };

template <int EPI>
__global__ __launch_bounds__(256, 2)
void gemm_mma(const __nv_bfloat16* __restrict__ AH, const __nv_bfloat16* __restrict__ AL,
              int ldA, int KC32,
              const __nv_bfloat16* __restrict__ WH, const __nv_bfloat16* __restrict__ WL,
              int ldW, int Nlog,
              const float* __restrict__ VinF,
              const __nv_bfloat16* __restrict__ VinH, const __nv_bfloat16* __restrict__ VinL,
              int ldV, float vscale,
              const float* __restrict__ Theta,
              const float* __restrict__ Ay, const float* __restrict__ By,
              __nv_bfloat16* __restrict__ OutH, __nv_bfloat16* __restrict__ OutL,
              float* __restrict__ OutF, int ldO)
{
    constexpr bool PAIR = (EPI == EP_AFF || EPI == EP_FINAL);
    constexpr int BN = 64;           // logical pair-columns per block (PAIR)
    constexpr int RB = 128;          // B rows per block
    constexpr int CH = 32768;        // chunk buffer bytes

    extern __shared__ __align__(16) char smraw[];
    const uint32_t sbRaw = smem_u32(smraw);
    const uint32_t abU   = (sbRaw + 1023u) & ~1023u;
    char* ab = smraw + (abU - sbRaw);

    const int tid = threadIdx.x, wid = tid >> 5, lane = tid & 31;
    const int m0 = blockIdx.x * 128;
    const int n0 = blockIdx.y * (PAIR ? BN : RB);

    const int wm = wid >> 2, wn = wid & 3;   // 2 x 4 warp grid, 64x32 tiles
    float acc[4][4][4];
#pragma unroll
    for (int a = 0; a < 4; ++a)
#pragma unroll
        for (int b = 0; b < 4; ++b)
#pragma unroll
            for (int c = 0; c < 4; ++c) acc[a][b][c] = 0.f;

    // ---- per-lane ldmatrix address bases (chunk-relative) ----
    uint32_t aoff[4], axr[4], boff[2], bxr[2];
#pragma unroll
    for (int t = 0; t < 4; ++t) {
        int r = wm * 64 + t * 16 + (lane & 15);
        uint32_t line = (uint32_t)((r & 63) * 128 + ((r >> 6) << 6));
        axr[t] = (line >> 3) & 0x70;
        aoff[t] = line;
    }
#pragma unroll
    for (int t = 0; t < 2; ++t) {
        int r = wn * 32 + ((lane >> 4) & 1) * 8 + (lane & 7) + t * 16;
        uint32_t line = (uint32_t)((r & 63) * 128 + ((r >> 6) << 6));
        bxr[t] = (line >> 3) & 0x70;
        boff[t] = line;
    }
    const uint32_t akb = ((lane >> 4) & 1) * 16;
    const uint32_t bkb = ((lane >> 3) & 1) * 16;

    // ---- chunk loader ----
    auto issue_chunk = [&](int c) {
        const uint32_t ub = abU + (uint32_t)(c % 3) * CH;
#pragma unroll
        for (int i = 0; i < 2; ++i) {          // A: 128 rows x 4 quads
            int idx = tid + i * 256;
            int r = idx >> 2, q = idx & 3;
            uint32_t off = (uint32_t)((r & 63) * 128 + ((r >> 6) << 6));
            uint32_t so = (off + q * 16) ^ ((off >> 3) & 0x70);
            size_t go = (size_t)(m0 + r) * ldA + c * 32 + q * 8;
            cp16(ub + so,        AH + go);
            cp16(ub + 8192 + so, AL + go);
        }
#pragma unroll
        for (int i = 0; i < 2; ++i) {          // B: 128 rows x 4 quads
            int idx = tid + i * 256;
            int r = idx >> 2, q = idx & 3;
            int wr, ok;
            if (PAIR) {
                if (r < BN) { int j = n0 + r;      ok = j < Nlog; wr = j; }
                else        { int j = n0 + r - BN; ok = j < Nlog; wr = Nlog + j; }
            } else { wr = n0 + r; ok = wr < Nlog; }
            int wrc = ok ? wr : 0;
            uint32_t sz = ok ? 16u : 0u;
            uint32_t off = (uint32_t)((r & 63) * 128 + ((r >> 6) << 6));
            uint32_t so = (off + q * 16) ^ ((off >> 3) & 0x70);
            size_t go = (size_t)wrc * ldW + c * 32 + q * 8;
            cp16z(ub + 16384 + so, WH + go, sz);
            cp16z(ub + 24576 + so, WL + go, sz);
        }
        cp_commit();
    };

    // ---- compute one k32 chunk ----
    auto compute = [&](int c) {
        const uint32_t uA  = abU + (uint32_t)(c % 3) * CH;
        const uint32_t uAl = uA + 8192, uB = uA + 16384, uBl = uA + 24576;
#pragma unroll
        for (int ks = 0; ks < 2; ++ks) {
            const uint32_t ka = ks * 32 + akb;
            const uint32_t kb = ks * 32 + bkb;
            uint32_t ah[4][4], al[4][4], bh[2][4], bl[2][4];
#pragma unroll
            for (int t = 0; t < 4; ++t) ldsm4(ah[t], uA + ((aoff[t] + ka) ^ axr[t]));
            ldsm4(bh[0], uB + ((boff[0] + kb) ^ bxr[0]));
            ldsm4(bh[1], uB + ((boff[1] + kb) ^ bxr[1]));
            ldsm4(bl[0], uBl + ((boff[0] + kb) ^ bxr[0]));
            ldsm4(bl[1], uBl + ((boff[1] + kb) ^ bxr[1]));
#pragma unroll
            for (int mt = 0; mt < 4; ++mt)
#pragma unroll
                for (int nt = 0; nt < 4; ++nt)
                    mma_bf16(acc[mt][nt], ah[mt], &bh[nt >> 1][(nt & 1) * 2]);
#pragma unroll
            for (int mt = 0; mt < 4; ++mt)
#pragma unroll
                for (int nt = 0; nt < 4; ++nt)
                    mma_bf16(acc[mt][nt], ah[mt], &bl[nt >> 1][(nt & 1) * 2]);
#pragma unroll
            for (int t = 0; t < 4; ++t) ldsm4(al[t], uAl + ((aoff[t] + ka) ^ axr[t]));
#pragma unroll
            for (int mt = 0; mt < 4; ++mt)
#pragma unroll
                for (int nt = 0; nt < 4; ++nt)
                    mma_bf16(acc[mt][nt], al[mt], &bh[nt >> 1][(nt & 1) * 2]);
        }
    };

    // ---- multistage mainloop: one sync per chunk, 2 chunks in flight ----
    issue_chunk(0);
    if (KC32 > 1) issue_chunk(1);
#pragma unroll 1
    for (int c = 0; c < KC32; ++c) {
        if (c + 1 < KC32) cp_wait<1>(); else cp_wait<0>();
        __syncthreads();
        if (c + 2 < KC32) issue_chunk(c + 2);
        compute(c);
    }
    __syncthreads();

    // ---- dump accumulators to smem (aliases stage memory) ----
    constexpr int PITCH = 132;
    float* sAcc = reinterpret_cast<float*>(ab);
    {
        const int tr = lane >> 2, tc = (lane & 3) * 2;
#pragma unroll
        for (int mt = 0; mt < 4; ++mt)
#pragma unroll
            for (int nt = 0; nt < 4; ++nt) {
                int row = wm * 64 + mt * 16 + tr, col = wn * 32 + nt * 8 + tc;
                *reinterpret_cast<float2*>(&sAcc[row * PITCH + col]) =
                    make_float2(acc[mt][nt][0], acc[mt][nt][1]);
                *reinterpret_cast<float2*>(&sAcc[(row + 8) * PITCH + col]) =
                    make_float2(acc[mt][nt][2], acc[mt][nt][3]);
            }
    }
    __syncthreads();

    // ---- epilogue: lane -> column (coalesced gmem) ----
    if (EPI == EP_GELU || EPI == EP_TANHPI) {
        for (int r = wid; r < 128; r += 8) {
            size_t ro = (size_t)(m0 + r) * ldO;
            for (int c = lane; c < RB; c += 32) {
                if (n0 + c >= Nlog) break;
                float a0 = sAcc[r * PITCH + c];
                float v = (EPI == EP_GELU) ? gelu_tanh(a0) : CUDART_PI_F * tanhf(a0);
                if (OutF) OutF[ro + n0 + c] = v;
                else { __nv_bfloat16 h, l; split_bf(v, h, l);
                       OutH[ro + n0 + c] = h; OutL[ro + n0 + c] = l; }
            }
        }
    } else if (EPI == EP_AFF) {
        for (int r = wid; r < 128; r += 8) {
            size_t rv = (size_t)(m0 + r) * ldV, ro = (size_t)(m0 + r) * ldO;
            for (int c = lane; c < BN; c += 32) {
                int n = n0 + c;
                if (n >= Nlog) break;
                float vin = VinF ? VinF[rv + n] * vscale
                                 : __bfloat162float(VinH[rv + n]) +
                                   __bfloat162float(VinL[rv + n]);
                float a0 = sAcc[r * PITCH + c], t0 = sAcc[r * PITCH + BN + c];
                float v = vin * __expf(tanhf(a0)) + t0;
                if (OutF) OutF[ro + n] = v;
                else { __nv_bfloat16 h, l; split_bf(v, h, l);
                       OutH[ro + n] = h; OutL[ro + n] = l; }
            }
        }
    } else { // EP_FINAL
        for (int r = wid; r < 128; r += 8) {
            int gm = m0 + r, cch = gm & 63, bb = gm >> 6;
            size_t rv = (size_t)gm * ldV;
            for (int cp = lane; cp < BN / 2; cp += 32) {
                int j = cp * 2, n = n0 + j;
                if (n >= Nlog) break;
                int p = n >> 1;
                float a0 = sAcc[r * PITCH + j],      a1 = sAcc[r * PITCH + j + 1];
                float t0 = sAcc[r * PITCH + BN + j], t1 = sAcc[r * PITCH + BN + j + 1];
                float th = Theta[(size_t)gm * P2_ + p], sn, cs;
                sincosf(th, &sn, &cs);
                float av = Ay[cch * P2_ + p], bv = By[cch * P2_ + p];
                float rn = rsqrtf(av * av + bv * bv);
                float ca = av * rn, cb = bv * rn;
                float2 yv = *reinterpret_cast<const float2*>(VinF + rv + n);
                float r1 = cs * yv.x - sn * yv.y, i1 = sn * yv.x + cs * yv.y;
                float r2 = ca * r1 - cb * i1, i2 = cb * r1 + ca * i1;
                float r3 = r2 * __expf(tanhf(a0)), i3 = i2 * __expf(tanhf(a1));
                float r4 = ca * r3 + cb * i3,  i4 = -cb * r3 + ca * i3;
                float r5 = cs * r4 + sn * i4,  i5 = -sn * r4 + cs * i4;
                OutF[((size_t)bb * P_ + n) * C_ + cch]     = r5 + t0;
                OutF[((size_t)bb * P_ + n + 1) * C_ + cch] = i5 + t1;
            }
        }
    }
}

// ---------------- host ----------------
constexpr int SMEMSZ = 3 * 32768 + 1024;   // 3 chunks + align slack

extern "C" void kernel_launch(void* const* d_in, const int* in_sizes, int n_in,
                              void* d_out, int out_size)
{
    (void)in_sizes; (void)n_in; (void)out_size;
    const float* x_bsd = (const float*)d_in[0];
    const float* z0    = (const float*)d_in[1];
    const float* y0    = (const float*)d_in[2];
    const float* a_y   = (const float*)d_in[16];
    const float* b_y   = (const float*)d_in[17];
    float* out = (float*)d_out;

    __nv_bfloat16 *wph, *wpl, *xh, *xl, *hh, *hl, *zh, *zl;
    float *y, *th;
    cudaGetSymbolAddress((void**)&wph, g_wph);
    cudaGetSymbolAddress((void**)&wpl, g_wpl);
    cudaGetSymbolAddress((void**)&xh, g_xh);  cudaGetSymbolAddress((void**)&xl, g_xl);
    cudaGetSymbolAddress((void**)&hh, g_hh);  cudaGetSymbolAddress((void**)&hl, g_hl);
    cudaGetSymbolAddress((void**)&zh, g_zh);  cudaGetSymbolAddress((void**)&zl, g_zl);
    cudaGetSymbolAddress((void**)&y,  g_y);   cudaGetSymbolAddress((void**)&th, g_th);

    static bool attr_done = false;
    if (!attr_done) {
        cudaFuncSetAttribute(gemm_mma<EP_GELU>,   cudaFuncAttributeMaxDynamicSharedMemorySize, SMEMSZ);
        cudaFuncSetAttribute(gemm_mma<EP_TANHPI>, cudaFuncAttributeMaxDynamicSharedMemorySize, SMEMSZ);
        cudaFuncSetAttribute(gemm_mma<EP_AFF>,    cudaFuncAttributeMaxDynamicSharedMemorySize, SMEMSZ);
        cudaFuncSetAttribute(gemm_mma<EP_FINAL>,  cudaFuncAttributeMaxDynamicSharedMemorySize, SMEMSZ);
        attr_done = true;
    }

    // ---- merged weight conversion ----
    struct WS { int idx; int K, Nall, Kpad; size_t off; };
    const WS ws[12] = {
        {3, 720, 512, 768, OFF_WH},  {4, 512, 1024, 512, OFF_SSZ},
        {5, 720, 1024, 768, OFF_XZ2},{6, 720, 1024, 768, OFF_XZ3},
        {7, 720, 1024, 768, OFF_XZ4},{8, 720, 1024, 768, OFF_XZ5},
        {9, 512, 1440, 512, OFF_ZX0},{10,512, 1440, 512, OFF_ZX2},
        {11,512, 1440, 512, OFF_ZX3},{13,512, 672,  512, OFF_ZY},
        {14,512, 168,  512, OFF_ROT},{15,512, 672,  512, OFF_KOO},
    };
    ConvAll ca;
    int total = 0;
    for (int i = 0; i < 12; ++i) {
        ca.src[i]  = (const float*)d_in[ws[i].idx];
        ca.hi[i]   = wph + ws[i].off;
        ca.lo[i]   = wpl + ws[i].off;
        ca.K[i]    = ws[i].K;
        ca.Nall[i] = ws[i].Nall;
        ca.Kpad[i] = ws[i].Kpad;
        ca.base[i] = total;
        total += (ws[i].Kpad / 32) * ((ws[i].Nall + 31) / 32);
    }
    ca.base[12] = total;
    convert_all<<<total, dim3(32, 8)>>>(ca);
    convert_x<<<dim3(24, 2, 64), dim3(32, 8)>>>(x_bsd, xh, xl);

    const __nv_bfloat16* Z = nullptr; const float* ZF = nullptr;

    // ---- GEMM chain (W_zx_v5 branch dead in reference: skipped) ----
    // h = gelu(xT @ W_h)                        (x data ends at k=720 -> 23 chunks)
    gemm_mma<EP_GELU><<<dim3(32, 4), 256, SMEMSZ>>>(
        xh, xl, 768, 23, wph + OFF_WH, wpl + OFF_WH, 768, 512,
        ZF, Z, Z, 0, 0.f, ZF, ZF, ZF, hh, hl, nullptr, 512);
    // z = affine(0.1*z0 ; h @ W_ssz)
    gemm_mma<EP_AFF><<<dim3(32, 8), 256, SMEMSZ>>>(
        hh, hl, 512, 16, wph + OFF_SSZ, wpl + OFF_SSZ, 512, 512,
        z0, Z, Z, 512, 0.1f, ZF, ZF, ZF, zh, zl, nullptr, 512);
    // x = affine(xT ; z @ W_zx_v0)
    gemm_mma<EP_AFF><<<dim3(32, 12), 256, SMEMSZ>>>(
        zh, zl, 512, 16, wph + OFF_ZX0, wpl + OFF_ZX0, 512, 720,
        ZF, xh, xl, 768, 1.f, ZF, ZF, ZF, xh, xl, nullptr, 768);
    // z = affine(z ; x @ W_xz_v2)
    gemm_mma<EP_AFF><<<dim3(32, 8), 256, SMEMSZ>>>(
        xh, xl, 768, 23, wph + OFF_XZ2, wpl + OFF_XZ2, 768, 512,
        ZF, zh, zl, 512, 1.f, ZF, ZF, ZF, zh, zl, nullptr, 512);
    // x = affine(x ; z @ W_zx_v2)
    gemm_mma<EP_AFF><<<dim3(32, 12), 256, SMEMSZ>>>(
        zh, zl, 512, 16, wph + OFF_ZX2, wpl + OFF_ZX2, 512, 720,
        ZF, xh, xl, 768, 1.f, ZF, ZF, ZF, xh, xl, nullptr, 768);
    // z = affine(z ; x @ W_xz_v3)
    gemm_mma<EP_AFF><<<dim3(32, 8), 256, SMEMSZ>>>(
        xh, xl, 768, 23, wph + OFF_XZ3, wpl + OFF_XZ3, 768, 512,
        ZF, zh, zl, 512, 1.f, ZF, ZF, ZF, zh, zl, nullptr, 512);
    // x = affine(x ; z @ W_zx_v3)
    gemm_mma<EP_AFF><<<dim3(32, 12), 256, SMEMSZ>>>(
        zh, zl, 512, 16, wph + OFF_ZX3, wpl + OFF_ZX3, 512, 720,
        ZF, xh, xl, 768, 1.f, ZF, ZF, ZF, xh, xl, nullptr, 768);
    // z = affine(z ; x @ W_xz_v4)
    gemm_mma<EP_AFF><<<dim3(32, 8), 256, SMEMSZ>>>(
        xh, xl, 768, 23, wph + OFF_XZ4, wpl + OFF_XZ4, 768, 512,
        ZF, zh, zl, 512, 1.f, ZF, ZF, ZF, zh, zl, nullptr, 512);
    // y = affine(0.1*y0 ; z @ W_zy_v4)   (f32 out)
    gemm_mma<EP_AFF><<<dim3(32, 6), 256, SMEMSZ>>>(
        zh, zl, 512, 16, wph + OFF_ZY, wpl + OFF_ZY, 512, 336,
        y0, Z, Z, 336, 0.1f, ZF, ZF, ZF, nullptr, nullptr, y, 336);
    // z = affine(z ; x @ W_xz_v5)
    gemm_mma<EP_AFF><<<dim3(32, 8), 256, SMEMSZ>>>(
        xh, xl, 768, 23, wph + OFF_XZ5, wpl + OFF_XZ5, 768, 512,
        ZF, zh, zl, 512, 1.f, ZF, ZF, ZF, zh, zl, nullptr, 512);
    // theta = pi*tanh(z @ W_rot)         (f32 out)
    gemm_mma<EP_TANHPI><<<dim3(32, 2), 256, SMEMSZ>>>(
        zh, zl, 512, 16, wph + OFF_ROT, wpl + OFF_ROT, 512, 168,
        ZF, Z, Z, 0, 0.f, ZF, ZF, ZF, nullptr, nullptr, th, 168);
    // final: z @ W_koo -> scale/shift + rot/koop chain, transposed store
    gemm_mma<EP_FINAL><<<dim3(32, 6), 256, SMEMSZ>>>(
        zh, zl, 512, 16, wph + OFF_KOO, wpl + OFF_KOO, 512, 336,
        y, Z, Z, 336, 1.f, th, a_y, b_y, nullptr, nullptr, out, 0);
}

// round 11
// speedup vs baseline: 1.4030x; 1.0185x over previous
#include <cuda_runtime.h>
#include <cuda_bf16.h>
#include <math_constants.h>
#include <cstdint>

// ---------------- problem constants ----------------
constexpr int C_  = 64;
constexpr int L_  = 720;
constexpr int P_  = 336;
constexpr int P2_ = 168;
constexpr int M_  = 4096;   // B*C
constexpr int KPX = 768;    // 720 padded to 64

// ---------------- weight pool offsets (transposed [Nall][Kpad] bf16) -----
constexpr size_t OFF_WH  = 0;                 constexpr size_t SZ_WH  = 512  * 768;
constexpr size_t OFF_SSZ = OFF_WH  + SZ_WH;   constexpr size_t SZ_SSZ = 1024 * 512;
constexpr size_t OFF_XZ2 = OFF_SSZ + SZ_SSZ;  constexpr size_t SZ_XZ  = 1024 * 768;
constexpr size_t OFF_XZ3 = OFF_XZ2 + SZ_XZ;
constexpr size_t OFF_XZ4 = OFF_XZ3 + SZ_XZ;
constexpr size_t OFF_XZ5 = OFF_XZ4 + SZ_XZ;
constexpr size_t OFF_ZX0 = OFF_XZ5 + SZ_XZ;   constexpr size_t SZ_ZX  = 1440 * 512;
constexpr size_t OFF_ZX2 = OFF_ZX0 + SZ_ZX;
constexpr size_t OFF_ZX3 = OFF_ZX2 + SZ_ZX;
constexpr size_t OFF_ZY  = OFF_ZX3 + SZ_ZX;   constexpr size_t SZ_ZY  = 672 * 512;
constexpr size_t OFF_ROT = OFF_ZY  + SZ_ZY;   constexpr size_t SZ_ROT = 168 * 512;
constexpr size_t OFF_KOO = OFF_ROT + SZ_ROT;  constexpr size_t SZ_KOO = 672 * 512;
constexpr size_t POOL    = OFF_KOO + SZ_KOO;

// ---------------- static device scratch ----------------
__device__ __align__(128) __nv_bfloat16 g_wph[POOL];
__device__ __align__(128) __nv_bfloat16 g_wpl[POOL];
__device__ __align__(128) __nv_bfloat16 g_xh[M_ * KPX], g_xl[M_ * KPX];
__device__ __align__(128) __nv_bfloat16 g_hh[M_ * 512], g_hl[M_ * 512];
__device__ __align__(128) __nv_bfloat16 g_zh[M_ * 512], g_zl[M_ * 512];
__device__ __align__(128) float g_y [M_ * P_];
__device__ __align__(128) float g_th[M_ * P2_];

// ---------------- helpers ----------------
__device__ __forceinline__ uint32_t smem_u32(const void* p) {
    uint32_t a;
    asm("{ .reg .u64 t; cvta.to.shared.u64 t, %1; cvt.u32.u64 %0, t; }" : "=r"(a) : "l"(p));
    return a;
}
__device__ __forceinline__ void cp16(uint32_t dst, const void* src) {
    asm volatile("cp.async.cg.shared.global [%0], [%1], 16;" :: "r"(dst), "l"(src));
}
__device__ __forceinline__ void cp16z(uint32_t dst, const void* src, uint32_t sz) {
    asm volatile("cp.async.cg.shared.global [%0], [%1], 16, %2;"
                 :: "r"(dst), "l"(src), "r"(sz));
}
__device__ __forceinline__ void cp_commit() {
    asm volatile("cp.async.commit_group;" ::: "memory");
}
template <int N>
__device__ __forceinline__ void cp_wait() {
    asm volatile("cp.async.wait_group %0;" :: "n"(N) : "memory");
}
__device__ __forceinline__ void ldsm4(uint32_t* r, uint32_t a) {
    asm volatile("ldmatrix.sync.aligned.m8n8.x4.shared.b16 {%0,%1,%2,%3}, [%4];"
                 : "=r"(r[0]), "=r"(r[1]), "=r"(r[2]), "=r"(r[3]) : "r"(a));
}
__device__ __forceinline__ void mma_bf16(float* d, const uint32_t* a, const uint32_t* b) {
    asm volatile(
        "mma.sync.aligned.m16n8k16.row.col.f32.bf16.bf16.f32 "
        "{%0,%1,%2,%3}, {%4,%5,%6,%7}, {%8,%9}, {%0,%1,%2,%3};"
        : "+f"(d[0]), "+f"(d[1]), "+f"(d[2]), "+f"(d[3])
        : "r"(a[0]), "r"(a[1]), "r"(a[2]), "r"(a[3]), "r"(b[0]), "r"(b[1]));
}
__device__ __forceinline__ float gelu_tanh(float x) {
    float x3 = x * x * x;
    return 0.5f * x * (1.0f + tanhf(0.7978845608028654f * (x + 0.044715f * x3)));
}
__device__ __forceinline__ void split_bf(float v, __nv_bfloat16& h, __nv_bfloat16& l) {
    h = __float2bfloat16(v);
    l = __float2bfloat16(v - __bfloat162float(h));
}

// ---------------- merged prep: all 12 weights in one kernel --------------
struct ConvAll {
    const float* src[12];
    __nv_bfloat16* hi[12];
    __nv_bfloat16* lo[12];
    int K[12], Nall[12], Kpad[12];
    int base[13];
};

__global__ void convert_all(ConvAll a)
{
    __shared__ float t[32][33];
    int bid = blockIdx.x;
    int w = 0;
    while (bid >= a.base[w + 1]) ++w;
    int local = bid - a.base[w];
    const int K = a.K[w], Nall = a.Nall[w], Kpad = a.Kpad[w];
    const int tilesY = (Nall + 31) >> 5;
    const int k0 = (local / tilesY) * 32, n0 = (local % tilesY) * 32;
    const float* W = a.src[w];
    __nv_bfloat16* Hi = a.hi[w];
    __nv_bfloat16* Lo = a.lo[w];

    for (int i = threadIdx.y; i < 32; i += 8) {
        int k = k0 + i, n = n0 + threadIdx.x;
        t[i][threadIdx.x] = (k < K && n < Nall) ? W[(size_t)k * Nall + n] : 0.f;
    }
    __syncthreads();
    for (int i = threadIdx.y; i < 32; i += 8) {
        int n = n0 + i, k = k0 + threadIdx.x;
        if (n < Nall && k < Kpad) {
            __nv_bfloat16 h, l; split_bf(t[threadIdx.x][i], h, l);
            Hi[(size_t)n * Kpad + k] = h;
            Lo[(size_t)n * Kpad + k] = l;
        }
    }
}

// ---------------- prep: x_bsd [64][720][64] -> xT hi/lo [4096][768] ------
__global__ void convert_x(const float* __restrict__ X,
                          __nv_bfloat16* __restrict__ Hi, __nv_bfloat16* __restrict__ Lo)
{
    __shared__ float t[32][33];
    int l0 = blockIdx.x * 32, c0 = blockIdx.y * 32, b = blockIdx.z;
    for (int i = threadIdx.y; i < 32; i += 8) {
        int l = l0 + i;
        t[i][threadIdx.x] = (l < L_) ? X[((size_t)b * L_ + l) * C_ + c0 + threadIdx.x] : 0.f;
    }
    __syncthreads();
    for (int i = threadIdx.y; i < 32; i += 8) {
        int c = c0 + i, l = l0 + threadIdx.x;
        __nv_bfloat16 h, lo; split_bf(t[threadIdx.x][i], h, lo);
        size_t o = (size_t)(b * 64 + c) * KPX + l;
        Hi[o] = h; Lo[o] = lo;
    }
}

// -- fused mma.sync GEMM: 64x128 tile, 8 warps (32x32), 3-deep k32 pipeline,
//    3 CTAs/SM.  Chunk (24KB): Ah 4K | Al 4K | Bh 8K | Bl 8K.
//    A rows (64B of k32) packed two-per-128B-line: line=r&31, half=r>>5.
//    B rows: line=r&63, half=r>>6.  SW128 swizzled.
enum { EP_GELU = 0, EP_TANHPI = 1, EP_AFF = 2, EP_FINAL = 3 };

template <int EPI>
__global__ __launch_bounds__(256, 3)
void gemm_mma(const __nv_bfloat16* __restrict__ AH, const __nv_bfloat16* __restrict__ AL,
              int ldA, int KC32,
              const __nv_bfloat16* __restrict__ WH, const __nv_bfloat16* __restrict__ WL,
              int ldW, int Nlog,
              const float* __restrict__ VinF,
              const __nv_bfloat16* __restrict__ VinH, const __nv_bfloat16* __restrict__ VinL,
              int ldV, float vscale,
              const float* __restrict__ Theta,
              const float* __restrict__ Ay, const float* __restrict__ By,
              __nv_bfloat16* __restrict__ OutH, __nv_bfloat16* __restrict__ OutL,
              float* __restrict__ OutF, int ldO)
{
    constexpr bool PAIR = (EPI == EP_AFF || EPI == EP_FINAL);
    constexpr int BN = 64;           // logical pair-columns per block (PAIR)
    constexpr int RB = 128;          // B rows per block
    constexpr int CH = 24576;        // chunk buffer bytes

    extern __shared__ __align__(16) char smraw[];
    const uint32_t sbRaw = smem_u32(smraw);
    const uint32_t abU   = (sbRaw + 1023u) & ~1023u;
    char* ab = smraw + (abU - sbRaw);

    const int tid = threadIdx.x, wid = tid >> 5, lane = tid & 31;
    const int m0 = blockIdx.x * 64;
    const int n0 = blockIdx.y * (PAIR ? BN : RB);

    const int wm = wid >> 2, wn = wid & 3;   // 2 x 4 warp grid, 32x32 tiles
    float acc[2][4][4];
#pragma unroll
    for (int a = 0; a < 2; ++a)
#pragma unroll
        for (int b = 0; b < 4; ++b)
#pragma unroll
            for (int c = 0; c < 4; ++c) acc[a][b][c] = 0.f;

    // ---- per-lane ldmatrix address bases (chunk-relative) ----
    uint32_t aoff[2], axr[2], boff[2], bxr[2];
#pragma unroll
    for (int t = 0; t < 2; ++t) {
        int r = wm * 32 + t * 16 + (lane & 15);
        uint32_t line = (uint32_t)((r & 31) * 128 + ((r >> 5) << 6));
        axr[t] = (line >> 3) & 0x70;
        aoff[t] = line;
    }
#pragma unroll
    for (int t = 0; t < 2; ++t) {
        int r = wn * 32 + ((lane >> 4) & 1) * 8 + (lane & 7) + t * 16;
        uint32_t line = (uint32_t)((r & 63) * 128 + ((r >> 6) << 6));
        bxr[t] = (line >> 3) & 0x70;
        boff[t] = line;
    }
    const uint32_t akb = ((lane >> 4) & 1) * 16;
    const uint32_t bkb = ((lane >> 3) & 1) * 16;

    // ---- chunk loader ----
    auto issue_chunk = [&](int c) {
        const uint32_t ub = abU + (uint32_t)(c % 3) * CH;
        {                                      // A: 64 rows x 4 quads (1 pass)
            int r = tid >> 2, q = tid & 3;
            uint32_t off = (uint32_t)((r & 31) * 128 + ((r >> 5) << 6));
            uint32_t so = (off + q * 16) ^ ((off >> 3) & 0x70);
            size_t go = (size_t)(m0 + r) * ldA + c * 32 + q * 8;
            cp16(ub + so,        AH + go);
            cp16(ub + 4096 + so, AL + go);
        }
#pragma unroll
        for (int i = 0; i < 2; ++i) {          // B: 128 rows x 4 quads
            int idx = tid + i * 256;
            int r = idx >> 2, q = idx & 3;
            int wr, ok;
            if (PAIR) {
                if (r < BN) { int j = n0 + r;      ok = j < Nlog; wr = j; }
                else        { int j = n0 + r - BN; ok = j < Nlog; wr = Nlog + j; }
            } else { wr = n0 + r; ok = wr < Nlog; }
            int wrc = ok ? wr : 0;
            uint32_t sz = ok ? 16u : 0u;
            uint32_t off = (uint32_t)((r & 63) * 128 + ((r >> 6) << 6));
            uint32_t so = (off + q * 16) ^ ((off >> 3) & 0x70);
            size_t go = (size_t)wrc * ldW + c * 32 + q * 8;
            cp16z(ub + 8192 + so,  WH + go, sz);
            cp16z(ub + 16384 + so, WL + go, sz);
        }
        cp_commit();
    };

    // ---- compute one k32 chunk ----
    auto compute = [&](int c) {
        const uint32_t uA  = abU + (uint32_t)(c % 3) * CH;
        const uint32_t uAl = uA + 4096, uB = uA + 8192, uBl = uA + 16384;
#pragma unroll
        for (int ks = 0; ks < 2; ++ks) {
            const uint32_t ka = ks * 32 + akb;
            const uint32_t kb = ks * 32 + bkb;
            uint32_t ah[2][4], al[2][4], bh[2][4], bl[2][4];
            ldsm4(ah[0], uA + ((aoff[0] + ka) ^ axr[0]));
            ldsm4(ah[1], uA + ((aoff[1] + ka) ^ axr[1]));
            ldsm4(bh[0], uB + ((boff[0] + kb) ^ bxr[0]));
            ldsm4(bh[1], uB + ((boff[1] + kb) ^ bxr[1]));
            ldsm4(bl[0], uBl + ((boff[0] + kb) ^ bxr[0]));
            ldsm4(bl[1], uBl + ((boff[1] + kb) ^ bxr[1]));
#pragma unroll
            for (int mt = 0; mt < 2; ++mt)
#pragma unroll
                for (int nt = 0; nt < 4; ++nt)
                    mma_bf16(acc[mt][nt], ah[mt], &bh[nt >> 1][(nt & 1) * 2]);
#pragma unroll
            for (int mt = 0; mt < 2; ++mt)
#pragma unroll
                for (int nt = 0; nt < 4; ++nt)
                    mma_bf16(acc[mt][nt], ah[mt], &bl[nt >> 1][(nt & 1) * 2]);
            ldsm4(al[0], uAl + ((aoff[0] + ka) ^ axr[0]));
            ldsm4(al[1], uAl + ((aoff[1] + ka) ^ axr[1]));
#pragma unroll
            for (int mt = 0; mt < 2; ++mt)
#pragma unroll
                for (int nt = 0; nt < 4; ++nt)
                    mma_bf16(acc[mt][nt], al[mt], &bh[nt >> 1][(nt & 1) * 2]);
        }
    };

    // ---- multistage mainloop: one sync per chunk, 2 chunks in flight ----
    issue_chunk(0);
    if (KC32 > 1) issue_chunk(1);
#pragma unroll 1
    for (int c = 0; c < KC32; ++c) {
        if (c + 1 < KC32) cp_wait<1>(); else cp_wait<0>();
        __syncthreads();
        if (c + 2 < KC32) issue_chunk(c + 2);
        compute(c);
    }
    __syncthreads();

    // ---- dump accumulators to smem (aliases stage memory) ----
    constexpr int PITCH = 132;
    float* sAcc = reinterpret_cast<float*>(ab);
    {
        const int tr = lane >> 2, tc = (lane & 3) * 2;
#pragma unroll
        for (int mt = 0; mt < 2; ++mt)
#pragma unroll
            for (int nt = 0; nt < 4; ++nt) {
                int row = wm * 32 + mt * 16 + tr, col = wn * 32 + nt * 8 + tc;
                *reinterpret_cast<float2*>(&sAcc[row * PITCH + col]) =
                    make_float2(acc[mt][nt][0], acc[mt][nt][1]);
                *reinterpret_cast<float2*>(&sAcc[(row + 8) * PITCH + col]) =
                    make_float2(acc[mt][nt][2], acc[mt][nt][3]);
            }
    }
    __syncthreads();

    // ---- epilogue: lane -> column (coalesced gmem) ----
    if (EPI == EP_GELU || EPI == EP_TANHPI) {
        for (int r = wid; r < 64; r += 8) {
            size_t ro = (size_t)(m0 + r) * ldO;
            for (int c = lane; c < RB; c += 32) {
                if (n0 + c >= Nlog) break;
                float a0 = sAcc[r * PITCH + c];
                float v = (EPI == EP_GELU) ? gelu_tanh(a0) : CUDART_PI_F * tanhf(a0);
                if (OutF) OutF[ro + n0 + c] = v;
                else { __nv_bfloat16 h, l; split_bf(v, h, l);
                       OutH[ro + n0 + c] = h; OutL[ro + n0 + c] = l; }
            }
        }
    } else if (EPI == EP_AFF) {
        for (int r = wid; r < 64; r += 8) {
            size_t rv = (size_t)(m0 + r) * ldV, ro = (size_t)(m0 + r) * ldO;
            for (int c = lane; c < BN; c += 32) {
                int n = n0 + c;
                if (n >= Nlog) break;
                float vin = VinF ? VinF[rv + n] * vscale
                                 : __bfloat162float(VinH[rv + n]) +
                                   __bfloat162float(VinL[rv + n]);
                float a0 = sAcc[r * PITCH + c], t0 = sAcc[r * PITCH + BN + c];
                float v = vin * __expf(tanhf(a0)) + t0;
                if (OutF) OutF[ro + n] = v;
                else { __nv_bfloat16 h, l; split_bf(v, h, l);
                       OutH[ro + n] = h; OutL[ro + n] = l; }
            }
        }
    } else { // EP_FINAL
        for (int r = wid; r < 64; r += 8) {
            int gm = m0 + r, cch = gm & 63, bb = gm >> 6;
            size_t rv = (size_t)gm * ldV;
            for (int cp = lane; cp < BN / 2; cp += 32) {
                int j = cp * 2, n = n0 + j;
                if (n >= Nlog) break;
                int p = n >> 1;
                float a0 = sAcc[r * PITCH + j],      a1 = sAcc[r * PITCH + j + 1];
                float t0 = sAcc[r * PITCH + BN + j], t1 = sAcc[r * PITCH + BN + j + 1];
                float th = Theta[(size_t)gm * P2_ + p], sn, cs;
                sincosf(th, &sn, &cs);
                float av = Ay[cch * P2_ + p], bv = By[cch * P2_ + p];
                float rn = rsqrtf(av * av + bv * bv);
                float ca = av * rn, cb = bv * rn;
                float2 yv = *reinterpret_cast<const float2*>(VinF + rv + n);
                float r1 = cs * yv.x - sn * yv.y, i1 = sn * yv.x + cs * yv.y;
                float r2 = ca * r1 - cb * i1, i2 = cb * r1 + ca * i1;
                float r3 = r2 * __expf(tanhf(a0)), i3 = i2 * __expf(tanhf(a1));
                float r4 = ca * r3 + cb * i3,  i4 = -cb * r3 + ca * i3;
                float r5 = cs * r4 + sn * i4,  i5 = -sn * r4 + cs * i4;
                OutF[((size_t)bb * P_ + n) * C_ + cch]     = r5 + t0;
                OutF[((size_t)bb * P_ + n + 1) * C_ + cch] = i5 + t1;
            }
        }
    }
}

// ---------------- host ----------------
constexpr int SMEMSZ = 3 * 24576 + 1024;   // 3 chunks + align slack (74752)

extern "C" void kernel_launch(void* const* d_in, const int* in_sizes, int n_in,
                              void* d_out, int out_size)
{
    (void)in_sizes; (void)n_in; (void)out_size;
    const float* x_bsd = (const float*)d_in[0];
    const float* z0    = (const float*)d_in[1];
    const float* y0    = (const float*)d_in[2];
    const float* a_y   = (const float*)d_in[16];
    const float* b_y   = (const float*)d_in[17];
    float* out = (float*)d_out;

    __nv_bfloat16 *wph, *wpl, *xh, *xl, *hh, *hl, *zh, *zl;
    float *y, *th;
    cudaGetSymbolAddress((void**)&wph, g_wph);
    cudaGetSymbolAddress((void**)&wpl, g_wpl);
    cudaGetSymbolAddress((void**)&xh, g_xh);  cudaGetSymbolAddress((void**)&xl, g_xl);
    cudaGetSymbolAddress((void**)&hh, g_hh);  cudaGetSymbolAddress((void**)&hl, g_hl);
    cudaGetSymbolAddress((void**)&zh, g_zh);  cudaGetSymbolAddress((void**)&zl, g_zl);
    cudaGetSymbolAddress((void**)&y,  g_y);   cudaGetSymbolAddress((void**)&th, g_th);

    static bool attr_done = false;
    if (!attr_done) {
        cudaFuncSetAttribute(gemm_mma<EP_GELU>,   cudaFuncAttributeMaxDynamicSharedMemorySize, SMEMSZ);
        cudaFuncSetAttribute(gemm_mma<EP_TANHPI>, cudaFuncAttributeMaxDynamicSharedMemorySize, SMEMSZ);
        cudaFuncSetAttribute(gemm_mma<EP_AFF>,    cudaFuncAttributeMaxDynamicSharedMemorySize, SMEMSZ);
        cudaFuncSetAttribute(gemm_mma<EP_FINAL>,  cudaFuncAttributeMaxDynamicSharedMemorySize, SMEMSZ);
        attr_done = true;
    }

    // ---- merged weight conversion ----
    struct WS { int idx; int K, Nall, Kpad; size_t off; };
    const WS ws[12] = {
        {3, 720, 512, 768, OFF_WH},  {4, 512, 1024, 512, OFF_SSZ},
        {5, 720, 1024, 768, OFF_XZ2},{6, 720, 1024, 768, OFF_XZ3},
        {7, 720, 1024, 768, OFF_XZ4},{8, 720, 1024, 768, OFF_XZ5},
        {9, 512, 1440, 512, OFF_ZX0},{10,512, 1440, 512, OFF_ZX2},
        {11,512, 1440, 512, OFF_ZX3},{13,512, 672,  512, OFF_ZY},
        {14,512, 168,  512, OFF_ROT},{15,512, 672,  512, OFF_KOO},
    };
    ConvAll ca;
    int total = 0;
    for (int i = 0; i < 12; ++i) {
        ca.src[i]  = (const float*)d_in[ws[i].idx];
        ca.hi[i]   = wph + ws[i].off;
        ca.lo[i]   = wpl + ws[i].off;
        ca.K[i]    = ws[i].K;
        ca.Nall[i] = ws[i].Nall;
        ca.Kpad[i] = ws[i].Kpad;
        ca.base[i] = total;
        total += (ws[i].Kpad / 32) * ((ws[i].Nall + 31) / 32);
    }
    ca.base[12] = total;
    convert_all<<<total, dim3(32, 8)>>>(ca);
    convert_x<<<dim3(24, 2, 64), dim3(32, 8)>>>(x_bsd, xh, xl);

    const __nv_bfloat16* Z = nullptr; const float* ZF = nullptr;

    // ---- GEMM chain (W_zx_v5 branch dead in reference: skipped) ----
    // h = gelu(xT @ W_h)                        (x data ends at k=720 -> 23 chunks)
    gemm_mma<EP_GELU><<<dim3(64, 4), 256, SMEMSZ>>>(
        xh, xl, 768, 23, wph + OFF_WH, wpl + OFF_WH, 768, 512,
        ZF, Z, Z, 0, 0.f, ZF, ZF, ZF, hh, hl, nullptr, 512);
    // z = affine(0.1*z0 ; h @ W_ssz)
    gemm_mma<EP_AFF><<<dim3(64, 8), 256, SMEMSZ>>>(
        hh, hl, 512, 16, wph + OFF_SSZ, wpl + OFF_SSZ, 512, 512,
        z0, Z, Z, 512, 0.1f, ZF, ZF, ZF, zh, zl, nullptr, 512);
    // x = affine(xT ; z @ W_zx_v0)
    gemm_mma<EP_AFF><<<dim3(64, 12), 256, SMEMSZ>>>(
        zh, zl, 512, 16, wph + OFF_ZX0, wpl + OFF_ZX0, 512, 720,
        ZF, xh, xl, 768, 1.f, ZF, ZF, ZF, xh, xl, nullptr, 768);
    // z = affine(z ; x @ W_xz_v2)
    gemm_mma<EP_AFF><<<dim3(64, 8), 256, SMEMSZ>>>(
        xh, xl, 768, 23, wph + OFF_XZ2, wpl + OFF_XZ2, 768, 512,
        ZF, zh, zl, 512, 1.f, ZF, ZF, ZF, zh, zl, nullptr, 512);
    // x = affine(x ; z @ W_zx_v2)
    gemm_mma<EP_AFF><<<dim3(64, 12), 256, SMEMSZ>>>(
        zh, zl, 512, 16, wph + OFF_ZX2, wpl + OFF_ZX2, 512, 720,
        ZF, xh, xl, 768, 1.f, ZF, ZF, ZF, xh, xl, nullptr, 768);
    // z = affine(z ; x @ W_xz_v3)
    gemm_mma<EP_AFF><<<dim3(64, 8), 256, SMEMSZ>>>(
        xh, xl, 768, 23, wph + OFF_XZ3, wpl + OFF_XZ3, 768, 512,
        ZF, zh, zl, 512, 1.f, ZF, ZF, ZF, zh, zl, nullptr, 512);
    // x = affine(x ; z @ W_zx_v3)
    gemm_mma<EP_AFF><<<dim3(64, 12), 256, SMEMSZ>>>(
        zh, zl, 512, 16, wph + OFF_ZX3, wpl + OFF_ZX3, 512, 720,
        ZF, xh, xl, 768, 1.f, ZF, ZF, ZF, xh, xl, nullptr, 768);
    // z = affine(z ; x @ W_xz_v4)
    gemm_mma<EP_AFF><<<dim3(64, 8), 256, SMEMSZ>>>(
        xh, xl, 768, 23, wph + OFF_XZ4, wpl + OFF_XZ4, 768, 512,
        ZF, zh, zl, 512, 1.f, ZF, ZF, ZF, zh, zl, nullptr, 512);
    // y = affine(0.1*y0 ; z @ W_zy_v4)   (f32 out)
    gemm_mma<EP_AFF><<<dim3(64, 6), 256, SMEMSZ>>>(
        zh, zl, 512, 16, wph + OFF_ZY, wpl + OFF_ZY, 512, 336,
        y0, Z, Z, 336, 0.1f, ZF, ZF, ZF, nullptr, nullptr, y, 336);
    // z = affine(z ; x @ W_xz_v5)
    gemm_mma<EP_AFF><<<dim3(64, 8), 256, SMEMSZ>>>(
        xh, xl, 768, 23, wph + OFF_XZ5, wpl + OFF_XZ5, 768, 512,
        ZF, zh, zl, 512, 1.f, ZF, ZF, ZF, zh, zl, nullptr, 512);
    // theta = pi*tanh(z @ W_rot)         (f32 out)
    gemm_mma<EP_TANHPI><<<dim3(64, 2), 256, SMEMSZ>>>(
        zh, zl, 512, 16, wph + OFF_ROT, wpl + OFF_ROT, 512, 168,
        ZF, Z, Z, 0, 0.f, ZF, ZF, ZF, nullptr, nullptr, th, 168);
    // final: z @ W_koo -> scale/shift + rot/koop chain, transposed store
    gemm_mma<EP_FINAL><<<dim3(64, 6), 256, SMEMSZ>>>(
        zh, zl, 512, 16, wph + OFF_KOO, wpl + OFF_KOO, 512, 336,
        y, Z, Z, 336, 1.f, th, a_y, b_y, nullptr, nullptr, out, 0);
}

// round 13
// speedup vs baseline: 1.4151x; 1.0086x over previous
#include <cuda_runtime.h>
#include <cuda_bf16.h>
#include <math_constants.h>
#include <cstdint>

// ---------------- problem constants ----------------
constexpr int C_  = 64;
constexpr int L_  = 720;
constexpr int P_  = 336;
constexpr int P2_ = 168;
constexpr int M_  = 4096;   // B*C
constexpr int KPX = 768;    // 720 padded to 64

// ---------------- weight pool offsets (transposed [Nall][Kpad] bf16) -----
constexpr size_t OFF_WH  = 0;                 constexpr size_t SZ_WH  = 512  * 768;
constexpr size_t OFF_SSZ = OFF_WH  + SZ_WH;   constexpr size_t SZ_SSZ = 1024 * 512;
constexpr size_t OFF_XZ2 = OFF_SSZ + SZ_SSZ;  constexpr size_t SZ_XZ  = 1024 * 768;
constexpr size_t OFF_XZ3 = OFF_XZ2 + SZ_XZ;
constexpr size_t OFF_XZ4 = OFF_XZ3 + SZ_XZ;
constexpr size_t OFF_XZ5 = OFF_XZ4 + SZ_XZ;
constexpr size_t OFF_ZX0 = OFF_XZ5 + SZ_XZ;   constexpr size_t SZ_ZX  = 1440 * 512;
constexpr size_t OFF_ZX2 = OFF_ZX0 + SZ_ZX;
constexpr size_t OFF_ZX3 = OFF_ZX2 + SZ_ZX;
constexpr size_t OFF_ZY  = OFF_ZX3 + SZ_ZX;   constexpr size_t SZ_ZY  = 672 * 512;
constexpr size_t OFF_ROT = OFF_ZY  + SZ_ZY;   constexpr size_t SZ_ROT = 168 * 512;
constexpr size_t OFF_KOO = OFF_ROT + SZ_ROT;  constexpr size_t SZ_KOO = 672 * 512;
constexpr size_t POOL    = OFF_KOO + SZ_KOO;

// ---------------- static device scratch ----------------
__device__ __align__(128) __nv_bfloat16 g_wph[POOL];
__device__ __align__(128) __nv_bfloat16 g_wpl[POOL];
__device__ __align__(128) __nv_bfloat16 g_xh[M_ * KPX], g_xl[M_ * KPX];
__device__ __align__(128) __nv_bfloat16 g_hh[M_ * 512], g_hl[M_ * 512];
__device__ __align__(128) __nv_bfloat16 g_zh[M_ * 512], g_zl[M_ * 512];
__device__ __align__(128) float g_y [M_ * P_];
__device__ __align__(128) float g_th[M_ * P2_];

// ---------------- helpers ----------------
__device__ __forceinline__ uint32_t smem_u32(const void* p) {
    uint32_t a;
    asm("{ .reg .u64 t; cvta.to.shared.u64 t, %1; cvt.u32.u64 %0, t; }" : "=r"(a) : "l"(p));
    return a;
}
__device__ __forceinline__ void cp16(uint32_t dst, const void* src) {
    asm volatile("cp.async.cg.shared.global [%0], [%1], 16;" :: "r"(dst), "l"(src));
}
__device__ __forceinline__ void cp16z(uint32_t dst, const void* src, uint32_t sz) {
    asm volatile("cp.async.cg.shared.global [%0], [%1], 16, %2;"
                 :: "r"(dst), "l"(src), "r"(sz));
}
__device__ __forceinline__ void cp_commit() {
    asm volatile("cp.async.commit_group;" ::: "memory");
}
template <int N>
__device__ __forceinline__ void cp_wait() {
    asm volatile("cp.async.wait_group %0;" :: "n"(N) : "memory");
}
__device__ __forceinline__ void ldsm4(uint32_t* r, uint32_t a) {
    asm volatile("ldmatrix.sync.aligned.m8n8.x4.shared.b16 {%0,%1,%2,%3}, [%4];"
                 : "=r"(r[0]), "=r"(r[1]), "=r"(r[2]), "=r"(r[3]) : "r"(a));
}
__device__ __forceinline__ void mma_bf16(float* d, const uint32_t* a, const uint32_t* b) {
    asm volatile(
        "mma.sync.aligned.m16n8k16.row.col.f32.bf16.bf16.f32 "
        "{%0,%1,%2,%3}, {%4,%5,%6,%7}, {%8,%9}, {%0,%1,%2,%3};"
        : "+f"(d[0]), "+f"(d[1]), "+f"(d[2]), "+f"(d[3])
        : "r"(a[0]), "r"(a[1]), "r"(a[2]), "r"(a[3]), "r"(b[0]), "r"(b[1]));
}
__device__ __forceinline__ float gelu_tanh(float x) {
    float x3 = x * x * x;
    return 0.5f * x * (1.0f + tanhf(0.7978845608028654f * (x + 0.044715f * x3)));
}
__device__ __forceinline__ void split_bf(float v, __nv_bfloat16& h, __nv_bfloat16& l) {
    h = __float2bfloat16(v);
    l = __float2bfloat16(v - __bfloat162float(h));
}

// ---------------- merged prep: all 12 weights in one kernel --------------
struct ConvAll {
    const float* src[12];
    __nv_bfloat16* hi[12];
    __nv_bfloat16* lo[12];
    int K[12], Nall[12], Kpad[12];
    int base[13];
};

__global__ void convert_all(ConvAll a)
{
    __shared__ float t[32][33];
    int bid = blockIdx.x;
    int w = 0;
    while (bid >= a.base[w + 1]) ++w;
    int local = bid - a.base[w];
    const int K = a.K[w], Nall = a.Nall[w], Kpad = a.Kpad[w];
    const int tilesY = (Nall + 31) >> 5;
    const int k0 = (local / tilesY) * 32, n0 = (local % tilesY) * 32;
    const float* W = a.src[w];
    __nv_bfloat16* Hi = a.hi[w];
    __nv_bfloat16* Lo = a.lo[w];

    for (int i = threadIdx.y; i < 32; i += 8) {
        int k = k0 + i, n = n0 + threadIdx.x;
        t[i][threadIdx.x] = (k < K && n < Nall) ? W[(size_t)k * Nall + n] : 0.f;
    }
    __syncthreads();
    for (int i = threadIdx.y; i < 32; i += 8) {
        int n = n0 + i, k = k0 + threadIdx.x;
        if (n < Nall && k < Kpad) {
            __nv_bfloat16 h, l; split_bf(t[threadIdx.x][i], h, l);
            Hi[(size_t)n * Kpad + k] = h;
            Lo[(size_t)n * Kpad + k] = l;
        }
    }
}

// ---------------- prep: x_bsd [64][720][64] -> xT hi/lo [4096][768] ------
__global__ void convert_x(const float* __restrict__ X,
                          __nv_bfloat16* __restrict__ Hi, __nv_bfloat16* __restrict__ Lo)
{
    __shared__ float t[32][33];
    int l0 = blockIdx.x * 32, c0 = blockIdx.y * 32, b = blockIdx.z;
    for (int i = threadIdx.y; i < 32; i += 8) {
        int l = l0 + i;
        t[i][threadIdx.x] = (l < L_) ? X[((size_t)b * L_ + l) * C_ + c0 + threadIdx.x] : 0.f;
    }
    __syncthreads();
    for (int i = threadIdx.y; i < 32; i += 8) {
        int c = c0 + i, l = l0 + threadIdx.x;
        __nv_bfloat16 h, lo; split_bf(t[threadIdx.x][i], h, lo);
        size_t o = (size_t)(b * 64 + c) * KPX + l;
        Hi[o] = h; Lo[o] = lo;
    }
}

// -- fused mma.sync GEMM: 64x128 tile, 8 warps (32x32), 3-deep k32 pipeline,
//    3 CTAs/SM.  Chunk (24KB): Ah 4K | Al 4K | Bh 8K | Bl 8K.
//    A rows (64B of k32) packed two-per-128B-line: line=r&31, half=r>>5.
//    B rows: line=r&63, half=r>>6.  SW128 swizzled.
enum { EP_GELU = 0, EP_TANHPI = 1, EP_AFF = 2, EP_FINAL = 3 };

template <int EPI>
__global__ __launch_bounds__(256, 3)
void gemm_mma(const __nv_bfloat16* __restrict__ AH, const __nv_bfloat16* __restrict__ AL,
              int ldA, int KC32,
              const __nv_bfloat16* __restrict__ WH, const __nv_bfloat16* __restrict__ WL,
              int ldW, int Nlog,
              const float* __restrict__ VinF,
              const __nv_bfloat16* __restrict__ VinH, const __nv_bfloat16* __restrict__ VinL,
              int ldV, float vscale,
              const float* __restrict__ Theta,
              const float* __restrict__ Ay, const float* __restrict__ By,
              __nv_bfloat16* __restrict__ OutH, __nv_bfloat16* __restrict__ OutL,
              float* __restrict__ OutF, int ldO)
{
    constexpr bool PAIR = (EPI == EP_AFF || EPI == EP_FINAL);
    constexpr int BN = 64;           // logical pair-columns per block (PAIR)
    constexpr int RB = 128;          // B rows per block
    constexpr int CH = 24576;        // chunk buffer bytes

    extern __shared__ __align__(16) char smraw[];
    const uint32_t sbRaw = smem_u32(smraw);
    const uint32_t abU   = (sbRaw + 1023u) & ~1023u;
    char* ab = smraw + (abU - sbRaw);

    const int tid = threadIdx.x, wid = tid >> 5, lane = tid & 31;
    const int m0 = blockIdx.x * 64;
    const int n0 = blockIdx.y * (PAIR ? BN : RB);

    const int wm = wid >> 2, wn = wid & 3;   // 2 x 4 warp grid, 32x32 tiles
    float acc[2][4][4];
#pragma unroll
    for (int a = 0; a < 2; ++a)
#pragma unroll
        for (int b = 0; b < 4; ++b)
#pragma unroll
            for (int c = 0; c < 4; ++c) acc[a][b][c] = 0.f;

    // ---- per-lane ldmatrix address bases (chunk-relative) ----
    uint32_t aoff[2], axr[2], boff[2], bxr[2];
#pragma unroll
    for (int t = 0; t < 2; ++t) {
        int r = wm * 32 + t * 16 + (lane & 15);
        uint32_t line = (uint32_t)((r & 31) * 128 + ((r >> 5) << 6));
        axr[t] = (line >> 3) & 0x70;
        aoff[t] = line;
    }
#pragma unroll
    for (int t = 0; t < 2; ++t) {
        int r = wn * 32 + ((lane >> 4) & 1) * 8 + (lane & 7) + t * 16;
        uint32_t line = (uint32_t)((r & 63) * 128 + ((r >> 6) << 6));
        bxr[t] = (line >> 3) & 0x70;
        boff[t] = line;
    }
    const uint32_t akb = ((lane >> 4) & 1) * 16;
    const uint32_t bkb = ((lane >> 3) & 1) * 16;

    // ---- chunk loader ----
    auto issue_chunk = [&](int c) {
        const uint32_t ub = abU + (uint32_t)(c % 3) * CH;
        {                                      // A: 64 rows x 4 quads (1 pass)
            int r = tid >> 2, q = tid & 3;
            uint32_t off = (uint32_t)((r & 31) * 128 + ((r >> 5) << 6));
            uint32_t so = (off + q * 16) ^ ((off >> 3) & 0x70);
            size_t go = (size_t)(m0 + r) * ldA + c * 32 + q * 8;
            cp16(ub + so,        AH + go);
            cp16(ub + 4096 + so, AL + go);
        }
#pragma unroll
        for (int i = 0; i < 2; ++i) {          // B: 128 rows x 4 quads
            int idx = tid + i * 256;
            int r = idx >> 2, q = idx & 3;
            int wr, ok;
            if (PAIR) {
                if (r < BN) { int j = n0 + r;      ok = j < Nlog; wr = j; }
                else        { int j = n0 + r - BN; ok = j < Nlog; wr = Nlog + j; }
            } else { wr = n0 + r; ok = wr < Nlog; }
            int wrc = ok ? wr : 0;
            uint32_t sz = ok ? 16u : 0u;
            uint32_t off = (uint32_t)((r & 63) * 128 + ((r >> 6) << 6));
            uint32_t so = (off + q * 16) ^ ((off >> 3) & 0x70);
            size_t go = (size_t)wrc * ldW + c * 32 + q * 8;
            cp16z(ub + 8192 + so,  WH + go, sz);
            cp16z(ub + 16384 + so, WL + go, sz);
        }
        cp_commit();
    };

    // ---- compute one k32 chunk: ALL 10 LDSM issued up-front (max MLP),
    //      then 3x8 MMAs drain against completed scoreboards ----
    auto compute = [&](int c) {
        const uint32_t uA  = abU + (uint32_t)(c % 3) * CH;
        const uint32_t uAl = uA + 4096, uB = uA + 8192, uBl = uA + 16384;
#pragma unroll
        for (int ks = 0; ks < 2; ++ks) {
            const uint32_t ka = ks * 32 + akb;
            const uint32_t kb = ks * 32 + bkb;
            uint32_t ah[2][4], al[2][4], bh[2][4], bl[2][4];
            ldsm4(ah[0], uA  + ((aoff[0] + ka) ^ axr[0]));
            ldsm4(ah[1], uA  + ((aoff[1] + ka) ^ axr[1]));
            ldsm4(bh[0], uB  + ((boff[0] + kb) ^ bxr[0]));
            ldsm4(bh[1], uB  + ((boff[1] + kb) ^ bxr[1]));
            ldsm4(al[0], uAl + ((aoff[0] + ka) ^ axr[0]));
            ldsm4(al[1], uAl + ((aoff[1] + ka) ^ axr[1]));
            ldsm4(bl[0], uBl + ((boff[0] + kb) ^ bxr[0]));
            ldsm4(bl[1], uBl + ((boff[1] + kb) ^ bxr[1]));
#pragma unroll
            for (int mt = 0; mt < 2; ++mt)
#pragma unroll
                for (int nt = 0; nt < 4; ++nt)
                    mma_bf16(acc[mt][nt], ah[mt], &bh[nt >> 1][(nt & 1) * 2]);
#pragma unroll
            for (int mt = 0; mt < 2; ++mt)
#pragma unroll
                for (int nt = 0; nt < 4; ++nt)
                    mma_bf16(acc[mt][nt], al[mt], &bh[nt >> 1][(nt & 1) * 2]);
#pragma unroll
            for (int mt = 0; mt < 2; ++mt)
#pragma unroll
                for (int nt = 0; nt < 4; ++nt)
                    mma_bf16(acc[mt][nt], ah[mt], &bl[nt >> 1][(nt & 1) * 2]);
        }
    };

    // ---- multistage mainloop: one sync per chunk, 2 chunks in flight ----
    issue_chunk(0);
    if (KC32 > 1) issue_chunk(1);
#pragma unroll 1
    for (int c = 0; c < KC32; ++c) {
        if (c + 1 < KC32) cp_wait<1>(); else cp_wait<0>();
        __syncthreads();
        if (c + 2 < KC32) issue_chunk(c + 2);
        compute(c);
    }
    __syncthreads();

    // ---- dump accumulators to smem (aliases stage memory) ----
    constexpr int PITCH = 132;
    float* sAcc = reinterpret_cast<float*>(ab);
    {
        const int tr = lane >> 2, tc = (lane & 3) * 2;
#pragma unroll
        for (int mt = 0; mt < 2; ++mt)
#pragma unroll
            for (int nt = 0; nt < 4; ++nt) {
                int row = wm * 32 + mt * 16 + tr, col = wn * 32 + nt * 8 + tc;
                *reinterpret_cast<float2*>(&sAcc[row * PITCH + col]) =
                    make_float2(acc[mt][nt][0], acc[mt][nt][1]);
                *reinterpret_cast<float2*>(&sAcc[(row + 8) * PITCH + col]) =
                    make_float2(acc[mt][nt][2], acc[mt][nt][3]);
            }
    }
    __syncthreads();

    // ---- epilogue: lane -> column (coalesced gmem) ----
    if (EPI == EP_GELU || EPI == EP_TANHPI) {
        for (int r = wid; r < 64; r += 8) {
            size_t ro = (size_t)(m0 + r) * ldO;
            for (int c = lane; c < RB; c += 32) {
                if (n0 + c >= Nlog) break;
                float a0 = sAcc[r * PITCH + c];
                float v = (EPI == EP_GELU) ? gelu_tanh(a0) : CUDART_PI_F * tanhf(a0);
                if (OutF) OutF[ro + n0 + c] = v;
                else { __nv_bfloat16 h, l; split_bf(v, h, l);
                       OutH[ro + n0 + c] = h; OutL[ro + n0 + c] = l; }
            }
        }
    } else if (EPI == EP_AFF) {
        for (int r = wid; r < 64; r += 8) {
            size_t rv = (size_t)(m0 + r) * ldV, ro = (size_t)(m0 + r) * ldO;
            for (int c = lane; c < BN; c += 32) {
                int n = n0 + c;
                if (n >= Nlog) break;
                float vin = VinF ? VinF[rv + n] * vscale
                                 : __bfloat162float(VinH[rv + n]) +
                                   __bfloat162float(VinL[rv + n]);
                float a0 = sAcc[r * PITCH + c], t0 = sAcc[r * PITCH + BN + c];
                float v = vin * __expf(tanhf(a0)) + t0;
                if (OutF) OutF[ro + n] = v;
                else { __nv_bfloat16 h, l; split_bf(v, h, l);
                       OutH[ro + n] = h; OutL[ro + n] = l; }
            }
        }
    } else { // EP_FINAL
        for (int r = wid; r < 64; r += 8) {
            int gm = m0 + r, cch = gm & 63, bb = gm >> 6;
            size_t rv = (size_t)gm * ldV;
            for (int cp = lane; cp < BN / 2; cp += 32) {
                int j = cp * 2, n = n0 + j;
                if (n >= Nlog) break;
                int p = n >> 1;
                float a0 = sAcc[r * PITCH + j],      a1 = sAcc[r * PITCH + j + 1];
                float t0 = sAcc[r * PITCH + BN + j], t1 = sAcc[r * PITCH + BN + j + 1];
                float th = Theta[(size_t)gm * P2_ + p], sn, cs;
                sincosf(th, &sn, &cs);
                float av = Ay[cch * P2_ + p], bv = By[cch * P2_ + p];
                float rn = rsqrtf(av * av + bv * bv);
                float ca = av * rn, cb = bv * rn;
                float2 yv = *reinterpret_cast<const float2*>(VinF + rv + n);
                float r1 = cs * yv.x - sn * yv.y, i1 = sn * yv.x + cs * yv.y;
                float r2 = ca * r1 - cb * i1, i2 = cb * r1 + ca * i1;
                float r3 = r2 * __expf(tanhf(a0)), i3 = i2 * __expf(tanhf(a1));
                float r4 = ca * r3 + cb * i3,  i4 = -cb * r3 + ca * i3;
                float r5 = cs * r4 + sn * i4,  i5 = -sn * r4 + cs * i4;
                OutF[((size_t)bb * P_ + n) * C_ + cch]     = r5 + t0;
                OutF[((size_t)bb * P_ + n + 1) * C_ + cch] = i5 + t1;
            }
        }
    }
}

// ---------------- host ----------------
constexpr int SMEMSZ = 3 * 24576 + 1024;   // 3 chunks + align slack (74752)

extern "C" void kernel_launch(void* const* d_in, const int* in_sizes, int n_in,
                              void* d_out, int out_size)
{
    (void)in_sizes; (void)n_in; (void)out_size;
    const float* x_bsd = (const float*)d_in[0];
    const float* z0    = (const float*)d_in[1];
    const float* y0    = (const float*)d_in[2];
    const float* a_y   = (const float*)d_in[16];
    const float* b_y   = (const float*)d_in[17];
    float* out = (float*)d_out;

    __nv_bfloat16 *wph, *wpl, *xh, *xl, *hh, *hl, *zh, *zl;
    float *y, *th;
    cudaGetSymbolAddress((void**)&wph, g_wph);
    cudaGetSymbolAddress((void**)&wpl, g_wpl);
    cudaGetSymbolAddress((void**)&xh, g_xh);  cudaGetSymbolAddress((void**)&xl, g_xl);
    cudaGetSymbolAddress((void**)&hh, g_hh);  cudaGetSymbolAddress((void**)&hl, g_hl);
    cudaGetSymbolAddress((void**)&zh, g_zh);  cudaGetSymbolAddress((void**)&zl, g_zl);
    cudaGetSymbolAddress((void**)&y,  g_y);   cudaGetSymbolAddress((void**)&th, g_th);

    static bool attr_done = false;
    if (!attr_done) {
        cudaFuncSetAttribute(gemm_mma<EP_GELU>,   cudaFuncAttributeMaxDynamicSharedMemorySize, SMEMSZ);
        cudaFuncSetAttribute(gemm_mma<EP_TANHPI>, cudaFuncAttributeMaxDynamicSharedMemorySize, SMEMSZ);
        cudaFuncSetAttribute(gemm_mma<EP_AFF>,    cudaFuncAttributeMaxDynamicSharedMemorySize, SMEMSZ);
        cudaFuncSetAttribute(gemm_mma<EP_FINAL>,  cudaFuncAttributeMaxDynamicSharedMemorySize, SMEMSZ);
        attr_done = true;
    }

    // ---- merged weight conversion ----
    struct WS { int idx; int K, Nall, Kpad; size_t off; };
    const WS ws[12] = {
        {3, 720, 512, 768, OFF_WH},  {4, 512, 1024, 512, OFF_SSZ},
        {5, 720, 1024, 768, OFF_XZ2},{6, 720, 1024, 768, OFF_XZ3},
        {7, 720, 1024, 768, OFF_XZ4},{8, 720, 1024, 768, OFF_XZ5},
        {9, 512, 1440, 512, OFF_ZX0},{10,512, 1440, 512, OFF_ZX2},
        {11,512, 1440, 512, OFF_ZX3},{13,512, 672,  512, OFF_ZY},
        {14,512, 168,  512, OFF_ROT},{15,512, 672,  512, OFF_KOO},
    };
    ConvAll ca;
    int total = 0;
    for (int i = 0; i < 12; ++i) {
        ca.src[i]  = (const float*)d_in[ws[i].idx];
        ca.hi[i]   = wph + ws[i].off;
        ca.lo[i]   = wpl + ws[i].off;
        ca.K[i]    = ws[i].K;
        ca.Nall[i] = ws[i].Nall;
        ca.Kpad[i] = ws[i].Kpad;
        ca.base[i] = total;
        total += (ws[i].Kpad / 32) * ((ws[i].Nall + 31) / 32);
    }
    ca.base[12] = total;
    convert_all<<<total, dim3(32, 8)>>>(ca);
    convert_x<<<dim3(24, 2, 64), dim3(32, 8)>>>(x_bsd, xh, xl);

    const __nv_bfloat16* Z = nullptr; const float* ZF = nullptr;

    // ---- GEMM chain (W_zx_v5 branch dead in reference: skipped) ----
    // h = gelu(xT @ W_h)                        (x data ends at k=720 -> 23 chunks)
    gemm_mma<EP_GELU><<<dim3(64, 4), 256, SMEMSZ>>>(
        xh, xl, 768, 23, wph + OFF_WH, wpl + OFF_WH, 768, 512,
        ZF, Z, Z, 0, 0.f, ZF, ZF, ZF, hh, hl, nullptr, 512);
    // z = affine(0.1*z0 ; h @ W_ssz)
    gemm_mma<EP_AFF><<<dim3(64, 8), 256, SMEMSZ>>>(
        hh, hl, 512, 16, wph + OFF_SSZ, wpl + OFF_SSZ, 512, 512,
        z0, Z, Z, 512, 0.1f, ZF, ZF, ZF, zh, zl, nullptr, 512);
    // x = affine(xT ; z @ W_zx_v0)
    gemm_mma<EP_AFF><<<dim3(64, 12), 256, SMEMSZ>>>(
        zh, zl, 512, 16, wph + OFF_ZX0, wpl + OFF_ZX0, 512, 720,
        ZF, xh, xl, 768, 1.f, ZF, ZF, ZF, xh, xl, nullptr, 768);
    // z = affine(z ; x @ W_xz_v2)
    gemm_mma<EP_AFF><<<dim3(64, 8), 256, SMEMSZ>>>(
        xh, xl, 768, 23, wph + OFF_XZ2, wpl + OFF_XZ2, 768, 512,
        ZF, zh, zl, 512, 1.f, ZF, ZF, ZF, zh, zl, nullptr, 512);
    // x = affine(x ; z @ W_zx_v2)
    gemm_mma<EP_AFF><<<dim3(64, 12), 256, SMEMSZ>>>(
        zh, zl, 512, 16, wph + OFF_ZX2, wpl + OFF_ZX2, 512, 720,
        ZF, xh, xl, 768, 1.f, ZF, ZF, ZF, xh, xl, nullptr, 768);
    // z = affine(z ; x @ W_xz_v3)
    gemm_mma<EP_AFF><<<dim3(64, 8), 256, SMEMSZ>>>(
        xh, xl, 768, 23, wph + OFF_XZ3, wpl + OFF_XZ3, 768, 512,
        ZF, zh, zl, 512, 1.f, ZF, ZF, ZF, zh, zl, nullptr, 512);
    // x = affine(x ; z @ W_zx_v3)
    gemm_mma<EP_AFF><<<dim3(64, 12), 256, SMEMSZ>>>(
        zh, zl, 512, 16, wph + OFF_ZX3, wpl + OFF_ZX3, 512, 720,
        ZF, xh, xl, 768, 1.f, ZF, ZF, ZF, xh, xl, nullptr, 768);
    // z = affine(z ; x @ W_xz_v4)
    gemm_mma<EP_AFF><<<dim3(64, 8), 256, SMEMSZ>>>(
        xh, xl, 768, 23, wph + OFF_XZ4, wpl + OFF_XZ4, 768, 512,
        ZF, zh, zl, 512, 1.f, ZF, ZF, ZF, zh, zl, nullptr, 512);
    // y = affine(0.1*y0 ; z @ W_zy_v4)   (f32 out)
    gemm_mma<EP_AFF><<<dim3(64, 6), 256, SMEMSZ>>>(
        zh, zl, 512, 16, wph + OFF_ZY, wpl + OFF_ZY, 512, 336,
        y0, Z, Z, 336, 0.1f, ZF, ZF, ZF, nullptr, nullptr, y, 336);
    // z = affine(z ; x @ W_xz_v5)
    gemm_mma<EP_AFF><<<dim3(64, 8), 256, SMEMSZ>>>(
        xh, xl, 768, 23, wph + OFF_XZ5, wpl + OFF_XZ5, 768, 512,
        ZF, zh, zl, 512, 1.f, ZF, ZF, ZF, zh, zl, nullptr, 512);
    // theta = pi*tanh(z @ W_rot)         (f32 out)
    gemm_mma<EP_TANHPI><<<dim3(64, 2), 256, SMEMSZ>>>(
        zh, zl, 512, 16, wph + OFF_ROT, wpl + OFF_ROT, 512, 168,
        ZF, Z, Z, 0, 0.f, ZF, ZF, ZF, nullptr, nullptr, th, 168);
    // final: z @ W_koo -> scale/shift + rot/koop chain, transposed store
    gemm_mma<EP_FINAL><<<dim3(64, 6), 256, SMEMSZ>>>(
        zh, zl, 512, 16, wph + OFF_KOO, wpl + OFF_KOO, 512, 336,
        y, Z, Z, 336, 1.f, th, a_y, b_y, nullptr, nullptr, out, 0);
}

// round 14
// speedup vs baseline: 1.4333x; 1.0128x over previous
#include <cuda_runtime.h>
#include <cuda_bf16.h>
#include <math_constants.h>
#include <cstdint>

// ---------------- problem constants ----------------
constexpr int C_  = 64;
constexpr int L_  = 720;
constexpr int P_  = 336;
constexpr int P2_ = 168;
constexpr int M_  = 4096;   // B*C
constexpr int KPX = 768;    // 720 padded to 64

// ---------------- weight pool offsets (transposed [Nall][Kpad] bf16) -----
constexpr size_t OFF_WH  = 0;                 constexpr size_t SZ_WH  = 512  * 768;
constexpr size_t OFF_SSZ = OFF_WH  + SZ_WH;   constexpr size_t SZ_SSZ = 1024 * 512;
constexpr size_t OFF_XZ2 = OFF_SSZ + SZ_SSZ;  constexpr size_t SZ_XZ  = 1024 * 768;
constexpr size_t OFF_XZ3 = OFF_XZ2 + SZ_XZ;
constexpr size_t OFF_XZ4 = OFF_XZ3 + SZ_XZ;
constexpr size_t OFF_XZ5 = OFF_XZ4 + SZ_XZ;
constexpr size_t OFF_ZX0 = OFF_XZ5 + SZ_XZ;   constexpr size_t SZ_ZX  = 1440 * 512;
constexpr size_t OFF_ZX2 = OFF_ZX0 + SZ_ZX;
constexpr size_t OFF_ZX3 = OFF_ZX2 + SZ_ZX;
constexpr size_t OFF_ZY  = OFF_ZX3 + SZ_ZX;   constexpr size_t SZ_ZY  = 672 * 512;
constexpr size_t OFF_ROT = OFF_ZY  + SZ_ZY;   constexpr size_t SZ_ROT = 168 * 512;
constexpr size_t OFF_KOO = OFF_ROT + SZ_ROT;  constexpr size_t SZ_KOO = 672 * 512;
constexpr size_t POOL    = OFF_KOO + SZ_KOO;

// ---------------- static device scratch ----------------
__device__ __align__(128) __nv_bfloat16 g_wph[POOL];
__device__ __align__(128) __nv_bfloat16 g_wpl[POOL];
__device__ __align__(128) __nv_bfloat16 g_xh[M_ * KPX], g_xl[M_ * KPX];
__device__ __align__(128) __nv_bfloat16 g_hh[M_ * 512], g_hl[M_ * 512];
__device__ __align__(128) __nv_bfloat16 g_zh[M_ * 512], g_zl[M_ * 512];
__device__ __align__(128) float g_y [M_ * P_];
__device__ __align__(128) float g_th[M_ * P2_];

// ---------------- helpers ----------------
__device__ __forceinline__ uint32_t smem_u32(const void* p) {
    uint32_t a;
    asm("{ .reg .u64 t; cvta.to.shared.u64 t, %1; cvt.u32.u64 %0, t; }" : "=r"(a) : "l"(p));
    return a;
}
__device__ __forceinline__ void cp16(uint32_t dst, const void* src) {
    asm volatile("cp.async.cg.shared.global [%0], [%1], 16;" :: "r"(dst), "l"(src));
}
__device__ __forceinline__ void cp16z(uint32_t dst, const void* src, uint32_t sz) {
    asm volatile("cp.async.cg.shared.global [%0], [%1], 16, %2;"
                 :: "r"(dst), "l"(src), "r"(sz));
}
__device__ __forceinline__ void cp_commit() {
    asm volatile("cp.async.commit_group;" ::: "memory");
}
template <int N>
__device__ __forceinline__ void cp_wait() {
    asm volatile("cp.async.wait_group %0;" :: "n"(N) : "memory");
}
__device__ __forceinline__ void ldsm4(uint32_t* r, uint32_t a) {
    asm volatile("ldmatrix.sync.aligned.m8n8.x4.shared.b16 {%0,%1,%2,%3}, [%4];"
                 : "=r"(r[0]), "=r"(r[1]), "=r"(r[2]), "=r"(r[3]) : "r"(a));
}
__device__ __forceinline__ void mma_bf16(float* d, const uint32_t* a, const uint32_t* b) {
    asm volatile(
        "mma.sync.aligned.m16n8k16.row.col.f32.bf16.bf16.f32 "
        "{%0,%1,%2,%3}, {%4,%5,%6,%7}, {%8,%9}, {%0,%1,%2,%3};"
        : "+f"(d[0]), "+f"(d[1]), "+f"(d[2]), "+f"(d[3])
        : "r"(a[0]), "r"(a[1]), "r"(a[2]), "r"(a[3]), "r"(b[0]), "r"(b[1]));
}
__device__ __forceinline__ float gelu_tanh(float x) {
    float x3 = x * x * x;
    return 0.5f * x * (1.0f + tanhf(0.7978845608028654f * (x + 0.044715f * x3)));
}
__device__ __forceinline__ void split_bf(float v, __nv_bfloat16& h, __nv_bfloat16& l) {
    h = __float2bfloat16(v);
    l = __float2bfloat16(v - __bfloat162float(h));
}

// ---------------- merged prep: a subset of weights in one kernel ---------
struct ConvAll {
    const float* src[12];
    __nv_bfloat16* hi[12];
    __nv_bfloat16* lo[12];
    int K[12], Nall[12], Kpad[12];
    int base[13];
};

__global__ void convert_all(ConvAll a)
{
    __shared__ float t[32][33];
    int bid = blockIdx.x;
    int w = 0;
    while (bid >= a.base[w + 1]) ++w;
    int local = bid - a.base[w];
    const int K = a.K[w], Nall = a.Nall[w], Kpad = a.Kpad[w];
    const int tilesY = (Nall + 31) >> 5;
    const int k0 = (local / tilesY) * 32, n0 = (local % tilesY) * 32;
    const float* W = a.src[w];
    __nv_bfloat16* Hi = a.hi[w];
    __nv_bfloat16* Lo = a.lo[w];

    for (int i = threadIdx.y; i < 32; i += 8) {
        int k = k0 + i, n = n0 + threadIdx.x;
        t[i][threadIdx.x] = (k < K && n < Nall) ? W[(size_t)k * Nall + n] : 0.f;
    }
    __syncthreads();
    for (int i = threadIdx.y; i < 32; i += 8) {
        int n = n0 + i, k = k0 + threadIdx.x;
        if (n < Nall && k < Kpad) {
            __nv_bfloat16 h, l; split_bf(t[threadIdx.x][i], h, l);
            Hi[(size_t)n * Kpad + k] = h;
            Lo[(size_t)n * Kpad + k] = l;
        }
    }
}

// ---------------- prep: x_bsd [64][720][64] -> xT hi/lo [4096][768] ------
__global__ void convert_x(const float* __restrict__ X,
                          __nv_bfloat16* __restrict__ Hi, __nv_bfloat16* __restrict__ Lo)
{
    __shared__ float t[32][33];
    int l0 = blockIdx.x * 32, c0 = blockIdx.y * 32, b = blockIdx.z;
    for (int i = threadIdx.y; i < 32; i += 8) {
        int l = l0 + i;
        t[i][threadIdx.x] = (l < L_) ? X[((size_t)b * L_ + l) * C_ + c0 + threadIdx.x] : 0.f;
    }
    __syncthreads();
    for (int i = threadIdx.y; i < 32; i += 8) {
        int c = c0 + i, l = l0 + threadIdx.x;
        __nv_bfloat16 h, lo; split_bf(t[threadIdx.x][i], h, lo);
        size_t o = (size_t)(b * 64 + c) * KPX + l;
        Hi[o] = h; Lo[o] = lo;
    }
}

// -- fused mma.sync GEMM: 64x128 tile, 8 warps (32x32), 3-deep k32 pipeline,
//    3 CTAs/SM.  Chunk (24KB): Ah 4K | Al 4K | Bh 8K | Bl 8K.
enum { EP_GELU = 0, EP_TANHPI = 1, EP_AFF = 2, EP_FINAL = 3 };

template <int EPI>
__global__ __launch_bounds__(256, 3)
void gemm_mma(const __nv_bfloat16* __restrict__ AH, const __nv_bfloat16* __restrict__ AL,
              int ldA, int KC32,
              const __nv_bfloat16* __restrict__ WH, const __nv_bfloat16* __restrict__ WL,
              int ldW, int Nlog,
              const float* __restrict__ VinF,
              const __nv_bfloat16* __restrict__ VinH, const __nv_bfloat16* __restrict__ VinL,
              int ldV, float vscale,
              const float* __restrict__ Theta,
              const float* __restrict__ Ay, const float* __restrict__ By,
              __nv_bfloat16* __restrict__ OutH, __nv_bfloat16* __restrict__ OutL,
              float* __restrict__ OutF, int ldO)
{
    constexpr bool PAIR = (EPI == EP_AFF || EPI == EP_FINAL);
    constexpr int BN = 64;
    constexpr int RB = 128;
    constexpr int CH = 24576;

    extern __shared__ __align__(16) char smraw[];
    const uint32_t sbRaw = smem_u32(smraw);
    const uint32_t abU   = (sbRaw + 1023u) & ~1023u;
    char* ab = smraw + (abU - sbRaw);

    const int tid = threadIdx.x, wid = tid >> 5, lane = tid & 31;
    const int m0 = blockIdx.x * 64;
    const int n0 = blockIdx.y * (PAIR ? BN : RB);

    const int wm = wid >> 2, wn = wid & 3;
    float acc[2][4][4];
#pragma unroll
    for (int a = 0; a < 2; ++a)
#pragma unroll
        for (int b = 0; b < 4; ++b)
#pragma unroll
            for (int c = 0; c < 4; ++c) acc[a][b][c] = 0.f;

    uint32_t aoff[2], axr[2], boff[2], bxr[2];
#pragma unroll
    for (int t = 0; t < 2; ++t) {
        int r = wm * 32 + t * 16 + (lane & 15);
        uint32_t line = (uint32_t)((r & 31) * 128 + ((r >> 5) << 6));
        axr[t] = (line >> 3) & 0x70;
        aoff[t] = line;
    }
#pragma unroll
    for (int t = 0; t < 2; ++t) {
        int r = wn * 32 + ((lane >> 4) & 1) * 8 + (lane & 7) + t * 16;
        uint32_t line = (uint32_t)((r & 63) * 128 + ((r >> 6) << 6));
        bxr[t] = (line >> 3) & 0x70;
        boff[t] = line;
    }
    const uint32_t akb = ((lane >> 4) & 1) * 16;
    const uint32_t bkb = ((lane >> 3) & 1) * 16;

    auto issue_chunk = [&](int c) {
        const uint32_t ub = abU + (uint32_t)(c % 3) * CH;
        {
            int r = tid >> 2, q = tid & 3;
            uint32_t off = (uint32_t)((r & 31) * 128 + ((r >> 5) << 6));
            uint32_t so = (off + q * 16) ^ ((off >> 3) & 0x70);
            size_t go = (size_t)(m0 + r) * ldA + c * 32 + q * 8;
            cp16(ub + so,        AH + go);
            cp16(ub + 4096 + so, AL + go);
        }
#pragma unroll
        for (int i = 0; i < 2; ++i) {
            int idx = tid + i * 256;
            int r = idx >> 2, q = idx & 3;
            int wr, ok;
            if (PAIR) {
                if (r < BN) { int j = n0 + r;      ok = j < Nlog; wr = j; }
                else        { int j = n0 + r - BN; ok = j < Nlog; wr = Nlog + j; }
            } else { wr = n0 + r; ok = wr < Nlog; }
            int wrc = ok ? wr : 0;
            uint32_t sz = ok ? 16u : 0u;
            uint32_t off = (uint32_t)((r & 63) * 128 + ((r >> 6) << 6));
            uint32_t so = (off + q * 16) ^ ((off >> 3) & 0x70);
            size_t go = (size_t)wrc * ldW + c * 32 + q * 8;
            cp16z(ub + 8192 + so,  WH + go, sz);
            cp16z(ub + 16384 + so, WL + go, sz);
        }
        cp_commit();
    };

    auto compute = [&](int c) {
        const uint32_t uA  = abU + (uint32_t)(c % 3) * CH;
        const uint32_t uAl = uA + 4096, uB = uA + 8192, uBl = uA + 16384;
#pragma unroll
        for (int ks = 0; ks < 2; ++ks) {
            const uint32_t ka = ks * 32 + akb;
            const uint32_t kb = ks * 32 + bkb;
            uint32_t ah[2][4], al[2][4], bh[2][4], bl[2][4];
            ldsm4(ah[0], uA  + ((aoff[0] + ka) ^ axr[0]));
            ldsm4(ah[1], uA  + ((aoff[1] + ka) ^ axr[1]));
            ldsm4(bh[0], uB  + ((boff[0] + kb) ^ bxr[0]));
            ldsm4(bh[1], uB  + ((boff[1] + kb) ^ bxr[1]));
            ldsm4(al[0], uAl + ((aoff[0] + ka) ^ axr[0]));
            ldsm4(al[1], uAl + ((aoff[1] + ka) ^ axr[1]));
            ldsm4(bl[0], uBl + ((boff[0] + kb) ^ bxr[0]));
            ldsm4(bl[1], uBl + ((boff[1] + kb) ^ bxr[1]));
#pragma unroll
            for (int mt = 0; mt < 2; ++mt)
#pragma unroll
                for (int nt = 0; nt < 4; ++nt)
                    mma_bf16(acc[mt][nt], ah[mt], &bh[nt >> 1][(nt & 1) * 2]);
#pragma unroll
            for (int mt = 0; mt < 2; ++mt)
#pragma unroll
                for (int nt = 0; nt < 4; ++nt)
                    mma_bf16(acc[mt][nt], al[mt], &bh[nt >> 1][(nt & 1) * 2]);
#pragma unroll
            for (int mt = 0; mt < 2; ++mt)
#pragma unroll
                for (int nt = 0; nt < 4; ++nt)
                    mma_bf16(acc[mt][nt], ah[mt], &bl[nt >> 1][(nt & 1) * 2]);
        }
    };

    issue_chunk(0);
    if (KC32 > 1) issue_chunk(1);
#pragma unroll 1
    for (int c = 0; c < KC32; ++c) {
        if (c + 1 < KC32) cp_wait<1>(); else cp_wait<0>();
        __syncthreads();
        if (c + 2 < KC32) issue_chunk(c + 2);
        compute(c);
    }
    __syncthreads();

    constexpr int PITCH = 132;
    float* sAcc = reinterpret_cast<float*>(ab);
    {
        const int tr = lane >> 2, tc = (lane & 3) * 2;
#pragma unroll
        for (int mt = 0; mt < 2; ++mt)
#pragma unroll
            for (int nt = 0; nt < 4; ++nt) {
                int row = wm * 32 + mt * 16 + tr, col = wn * 32 + nt * 8 + tc;
                *reinterpret_cast<float2*>(&sAcc[row * PITCH + col]) =
                    make_float2(acc[mt][nt][0], acc[mt][nt][1]);
                *reinterpret_cast<float2*>(&sAcc[(row + 8) * PITCH + col]) =
                    make_float2(acc[mt][nt][2], acc[mt][nt][3]);
            }
    }
    __syncthreads();

    if (EPI == EP_GELU || EPI == EP_TANHPI) {
        for (int r = wid; r < 64; r += 8) {
            size_t ro = (size_t)(m0 + r) * ldO;
            for (int c = lane; c < RB; c += 32) {
                if (n0 + c >= Nlog) break;
                float a0 = sAcc[r * PITCH + c];
                float v = (EPI == EP_GELU) ? gelu_tanh(a0) : CUDART_PI_F * tanhf(a0);
                if (OutF) OutF[ro + n0 + c] = v;
                else { __nv_bfloat16 h, l; split_bf(v, h, l);
                       OutH[ro + n0 + c] = h; OutL[ro + n0 + c] = l; }
            }
        }
    } else if (EPI == EP_AFF) {
        for (int r = wid; r < 64; r += 8) {
            size_t rv = (size_t)(m0 + r) * ldV, ro = (size_t)(m0 + r) * ldO;
            for (int c = lane; c < BN; c += 32) {
                int n = n0 + c;
                if (n >= Nlog) break;
                float vin = VinF ? VinF[rv + n] * vscale
                                 : __bfloat162float(VinH[rv + n]) +
                                   __bfloat162float(VinL[rv + n]);
                float a0 = sAcc[r * PITCH + c], t0 = sAcc[r * PITCH + BN + c];
                float v = vin * __expf(tanhf(a0)) + t0;
                if (OutF) OutF[ro + n] = v;
                else { __nv_bfloat16 h, l; split_bf(v, h, l);
                       OutH[ro + n] = h; OutL[ro + n] = l; }
            }
        }
    } else { // EP_FINAL
        for (int r = wid; r < 64; r += 8) {
            int gm = m0 + r, cch = gm & 63, bb = gm >> 6;
            size_t rv = (size_t)gm * ldV;
            for (int cp = lane; cp < BN / 2; cp += 32) {
                int j = cp * 2, n = n0 + j;
                if (n >= Nlog) break;
                int p = n >> 1;
                float a0 = sAcc[r * PITCH + j],      a1 = sAcc[r * PITCH + j + 1];
                float t0 = sAcc[r * PITCH + BN + j], t1 = sAcc[r * PITCH + BN + j + 1];
                float th = Theta[(size_t)gm * P2_ + p], sn, cs;
                sincosf(th, &sn, &cs);
                float av = Ay[cch * P2_ + p], bv = By[cch * P2_ + p];
                float rn = rsqrtf(av * av + bv * bv);
                float ca = av * rn, cb = bv * rn;
                float2 yv = *reinterpret_cast<const float2*>(VinF + rv + n);
                float r1 = cs * yv.x - sn * yv.y, i1 = sn * yv.x + cs * yv.y;
                float r2 = ca * r1 - cb * i1, i2 = cb * r1 + ca * i1;
                float r3 = r2 * __expf(tanhf(a0)), i3 = i2 * __expf(tanhf(a1));
                float r4 = ca * r3 + cb * i3,  i4 = -cb * r3 + ca * i3;
                float r5 = cs * r4 + sn * i4,  i5 = -sn * r4 + cs * i4;
                OutF[((size_t)bb * P_ + n) * C_ + cch]     = r5 + t0;
                OutF[((size_t)bb * P_ + n + 1) * C_ + cch] = i5 + t1;
            }
        }
    }
}

// ---------------- host ----------------
constexpr int SMEMSZ = 3 * 24576 + 1024;

extern "C" void kernel_launch(void* const* d_in, const int* in_sizes, int n_in,
                              void* d_out, int out_size)
{
    (void)in_sizes; (void)n_in; (void)out_size;
    const float* x_bsd = (const float*)d_in[0];
    const float* z0    = (const float*)d_in[1];
    const float* y0    = (const float*)d_in[2];
    const float* a_y   = (const float*)d_in[16];
    const float* b_y   = (const float*)d_in[17];
    float* out = (float*)d_out;

    __nv_bfloat16 *wph, *wpl, *xh, *xl, *hh, *hl, *zh, *zl;
    float *y, *th;
    cudaGetSymbolAddress((void**)&wph, g_wph);
    cudaGetSymbolAddress((void**)&wpl, g_wpl);
    cudaGetSymbolAddress((void**)&xh, g_xh);  cudaGetSymbolAddress((void**)&xl, g_xl);
    cudaGetSymbolAddress((void**)&hh, g_hh);  cudaGetSymbolAddress((void**)&hl, g_hl);
    cudaGetSymbolAddress((void**)&zh, g_zh);  cudaGetSymbolAddress((void**)&zl, g_zl);
    cudaGetSymbolAddress((void**)&y,  g_y);   cudaGetSymbolAddress((void**)&th, g_th);

    static cudaStream_t s2 = nullptr;
    static cudaEvent_t evWh = nullptr, evRest = nullptr, evZ4 = nullptr, evY = nullptr;
    static bool attr_done = false;
    if (!attr_done) {
        cudaFuncSetAttribute(gemm_mma<EP_GELU>,   cudaFuncAttributeMaxDynamicSharedMemorySize, SMEMSZ);
        cudaFuncSetAttribute(gemm_mma<EP_TANHPI>, cudaFuncAttributeMaxDynamicSharedMemorySize, SMEMSZ);
        cudaFuncSetAttribute(gemm_mma<EP_AFF>,    cudaFuncAttributeMaxDynamicSharedMemorySize, SMEMSZ);
        cudaFuncSetAttribute(gemm_mma<EP_FINAL>,  cudaFuncAttributeMaxDynamicSharedMemorySize, SMEMSZ);
        cudaStreamCreateWithFlags(&s2, cudaStreamNonBlocking);
        cudaEventCreateWithFlags(&evWh,   cudaEventDisableTiming);
        cudaEventCreateWithFlags(&evRest, cudaEventDisableTiming);
        cudaEventCreateWithFlags(&evZ4,   cudaEventDisableTiming);
        cudaEventCreateWithFlags(&evY,    cudaEventDisableTiming);
        attr_done = true;
    }

    struct WS { int idx; int K, Nall, Kpad; size_t off; };
    const WS ws[12] = {
        {3, 720, 512, 768, OFF_WH},  {4, 512, 1024, 512, OFF_SSZ},
        {5, 720, 1024, 768, OFF_XZ2},{6, 720, 1024, 768, OFF_XZ3},
        {7, 720, 1024, 768, OFF_XZ4},{8, 720, 1024, 768, OFF_XZ5},
        {9, 512, 1440, 512, OFF_ZX0},{10,512, 1440, 512, OFF_ZX2},
        {11,512, 1440, 512, OFF_ZX3},{13,512, 672,  512, OFF_ZY},
        {14,512, 168,  512, OFF_ROT},{15,512, 672,  512, OFF_KOO},
    };
    // W_h alone (needed first), rest batched separately.
    ConvAll cwh; ConvAll crest;
    {
        int i = 0;
        cwh.src[0]  = (const float*)d_in[ws[0].idx];
        cwh.hi[0]   = wph + ws[0].off; cwh.lo[0] = wpl + ws[0].off;
        cwh.K[0] = ws[0].K; cwh.Nall[0] = ws[0].Nall; cwh.Kpad[0] = ws[0].Kpad;
        int t0 = (ws[0].Kpad / 32) * ((ws[0].Nall + 31) / 32);
        cwh.base[0] = 0;
        for (int j = 1; j <= 12; ++j) cwh.base[j] = t0;
        int total = 0;
        for (i = 1; i < 12; ++i) {
            int k = i - 1;
            crest.src[k]  = (const float*)d_in[ws[i].idx];
            crest.hi[k]   = wph + ws[i].off; crest.lo[k] = wpl + ws[i].off;
            crest.K[k] = ws[i].K; crest.Nall[k] = ws[i].Nall; crest.Kpad[k] = ws[i].Kpad;
            crest.base[k] = total;
            total += (ws[i].Kpad / 32) * ((ws[i].Nall + 31) / 32);
        }
        for (int j = 11; j <= 12; ++j) crest.base[j] = total;

        const __nv_bfloat16* Z = nullptr; const float* ZF = nullptr;

        // ---- prep: W_h on s2, x-transpose on main, both feed the h-GEMM ----
        convert_x<<<dim3(24, 2, 64), dim3(32, 8), 0, 0>>>(x_bsd, xh, xl);
        cudaEventRecord(evWh, 0);                 // after convert_x on main
        cudaStreamWaitEvent(s2, evWh, 0);         // s2 joins capture
        convert_all<<<cwh.base[1], dim3(32, 8), 0, s2>>>(cwh);
        cudaEventRecord(evRest, s2);
        cudaStreamWaitEvent(0, evRest, 0);        // main waits for W_h

        // remaining 11 weight conversions hidden under the h-GEMM
        convert_all<<<total, dim3(32, 8), 0, s2>>>(crest);

        // h = gelu(xT @ W_h)
        gemm_mma<EP_GELU><<<dim3(64, 4), 256, SMEMSZ, 0>>>(
            xh, xl, 768, 23, wph + OFF_WH, wpl + OFF_WH, 768, 512,
            ZF, Z, Z, 0, 0.f, ZF, ZF, ZF, hh, hl, nullptr, 512);

        cudaEventRecord(evZ4, s2);                // end of convert_rest
        cudaStreamWaitEvent(0, evZ4, 0);          // main waits all weights

        // z1 = affine(0.1*z0 ; h @ W_ssz)
        gemm_mma<EP_AFF><<<dim3(64, 8), 256, SMEMSZ, 0>>>(
            hh, hl, 512, 16, wph + OFF_SSZ, wpl + OFF_SSZ, 512, 512,
            z0, Z, Z, 512, 0.1f, ZF, ZF, ZF, zh, zl, nullptr, 512);
        // x1 = affine(xT ; z1 @ W_zx_v0)
        gemm_mma<EP_AFF><<<dim3(64, 12), 256, SMEMSZ, 0>>>(
            zh, zl, 512, 16, wph + OFF_ZX0, wpl + OFF_ZX0, 512, 720,
            ZF, xh, xl, 768, 1.f, ZF, ZF, ZF, xh, xl, nullptr, 768);
        // z2 = affine(z1 ; x1 @ W_xz_v2)
        gemm_mma<EP_AFF><<<dim3(64, 8), 256, SMEMSZ, 0>>>(
            xh, xl, 768, 23, wph + OFF_XZ2, wpl + OFF_XZ2, 768, 512,
            ZF, zh, zl, 512, 1.f, ZF, ZF, ZF, zh, zl, nullptr, 512);
        // x2 = affine(x1 ; z2 @ W_zx_v2)
        gemm_mma<EP_AFF><<<dim3(64, 12), 256, SMEMSZ, 0>>>(
            zh, zl, 512, 16, wph + OFF_ZX2, wpl + OFF_ZX2, 512, 720,
            ZF, xh, xl, 768, 1.f, ZF, ZF, ZF, xh, xl, nullptr, 768);
        // z3 = affine(z2 ; x2 @ W_xz_v3)
        gemm_mma<EP_AFF><<<dim3(64, 8), 256, SMEMSZ, 0>>>(
            xh, xl, 768, 23, wph + OFF_XZ3, wpl + OFF_XZ3, 768, 512,
            ZF, zh, zl, 512, 1.f, ZF, ZF, ZF, zh, zl, nullptr, 512);
        // x3 = affine(x2 ; z3 @ W_zx_v3)
        gemm_mma<EP_AFF><<<dim3(64, 12), 256, SMEMSZ, 0>>>(
            zh, zl, 512, 16, wph + OFF_ZX3, wpl + OFF_ZX3, 512, 720,
            ZF, xh, xl, 768, 1.f, ZF, ZF, ZF, xh, xl, nullptr, 768);
        // z4 = affine(z3 ; x3 @ W_xz_v4)    -> zh/zl
        gemm_mma<EP_AFF><<<dim3(64, 8), 256, SMEMSZ, 0>>>(
            xh, xl, 768, 23, wph + OFF_XZ4, wpl + OFF_XZ4, 768, 512,
            ZF, zh, zl, 512, 1.f, ZF, ZF, ZF, zh, zl, nullptr, 512);

        // fork: y-GEMM (reads z4) runs on s2 concurrently with z5 + theta
        cudaEventRecord(evWh, 0);                 // reuse evWh as "z4 done"
        cudaStreamWaitEvent(s2, evWh, 0);
        // y = affine(0.1*y0 ; z4 @ W_zy_v4)  (f32 out) — on s2
        gemm_mma<EP_AFF><<<dim3(64, 6), 256, SMEMSZ, s2>>>(
            zh, zl, 512, 16, wph + OFF_ZY, wpl + OFF_ZY, 512, 336,
            y0, Z, Z, 336, 0.1f, ZF, ZF, ZF, nullptr, nullptr, y, 336);
        cudaEventRecord(evY, s2);

        // z5 = affine(z4 ; x3 @ W_xz_v5) -> hh/hl (NOT zh/zl: y still reads z4)
        gemm_mma<EP_AFF><<<dim3(64, 8), 256, SMEMSZ, 0>>>(
            xh, xl, 768, 23, wph + OFF_XZ5, wpl + OFF_XZ5, 768, 512,
            ZF, zh, zl, 512, 1.f, ZF, ZF, ZF, hh, hl, nullptr, 512);
        // theta = pi*tanh(z5 @ W_rot)
        gemm_mma<EP_TANHPI><<<dim3(64, 2), 256, SMEMSZ, 0>>>(
            hh, hl, 512, 16, wph + OFF_ROT, wpl + OFF_ROT, 512, 168,
            ZF, Z, Z, 0, 0.f, ZF, ZF, ZF, nullptr, nullptr, th, 168);

        cudaStreamWaitEvent(0, evY, 0);           // join y branch
        // final: z5 @ W_koo -> scale/shift + rot/koop chain, transposed store
        gemm_mma<EP_FINAL><<<dim3(64, 6), 256, SMEMSZ, 0>>>(
            hh, hl, 512, 16, wph + OFF_KOO, wpl + OFF_KOO, 512, 336,
            y, Z, Z, 336, 1.f, th, a_y, b_y, nullptr, nullptr, out, 0);
    }
}

// round 15
// speedup vs baseline: 1.6494x; 1.1508x over previous
#include <cuda_runtime.h>
#include <cuda_bf16.h>
#include <math_constants.h>
#include <cstdint>

// ---------------- problem constants ----------------
constexpr int C_  = 64;
constexpr int L_  = 720;
constexpr int P_  = 336;
constexpr int P2_ = 168;
constexpr int M_  = 4096;   // B*C
constexpr int KPX = 768;    // 720 padded to 64

// ---------------- weight pool offsets (transposed [Nall][Kpad] bf16) -----
constexpr size_t OFF_WH  = 0;                 constexpr size_t SZ_WH  = 512  * 768;
constexpr size_t OFF_SSZ = OFF_WH  + SZ_WH;   constexpr size_t SZ_SSZ = 1024 * 512;
constexpr size_t OFF_XZ2 = OFF_SSZ + SZ_SSZ;  constexpr size_t SZ_XZ  = 1024 * 768;
constexpr size_t OFF_XZ3 = OFF_XZ2 + SZ_XZ;
constexpr size_t OFF_XZ4 = OFF_XZ3 + SZ_XZ;
constexpr size_t OFF_XZ5 = OFF_XZ4 + SZ_XZ;
constexpr size_t OFF_ZX0 = OFF_XZ5 + SZ_XZ;   constexpr size_t SZ_ZX  = 1440 * 512;
constexpr size_t OFF_ZX2 = OFF_ZX0 + SZ_ZX;
constexpr size_t OFF_ZX3 = OFF_ZX2 + SZ_ZX;
constexpr size_t OFF_ZY  = OFF_ZX3 + SZ_ZX;   constexpr size_t SZ_ZY  = 672 * 512;
constexpr size_t OFF_ROT = OFF_ZY  + SZ_ZY;   constexpr size_t SZ_ROT = 168 * 512;
constexpr size_t OFF_KOO = OFF_ROT + SZ_ROT;  constexpr size_t SZ_KOO = 672 * 512;
constexpr size_t POOL    = OFF_KOO + SZ_KOO;

// ---------------- static device scratch ----------------
__device__ __align__(128) __nv_bfloat16 g_wph[POOL];
__device__ __align__(128) __nv_bfloat16 g_wpl[POOL];
__device__ __align__(128) __nv_bfloat16 g_xh[M_ * KPX], g_xl[M_ * KPX];
__device__ __align__(128) __nv_bfloat16 g_hh[M_ * 512], g_hl[M_ * 512];
__device__ __align__(128) __nv_bfloat16 g_zh[M_ * 512], g_zl[M_ * 512];
__device__ __align__(128) float g_y [M_ * P_];
__device__ __align__(128) float g_th[M_ * P2_];

// ---------------- helpers ----------------
__device__ __forceinline__ uint32_t smem_u32(const void* p) {
    uint32_t a;
    asm("{ .reg .u64 t; cvta.to.shared.u64 t, %1; cvt.u32.u64 %0, t; }" : "=r"(a) : "l"(p));
    return a;
}
__device__ __forceinline__ void cp16(uint32_t dst, const void* src) {
    asm volatile("cp.async.cg.shared.global [%0], [%1], 16;" :: "r"(dst), "l"(src));
}
__device__ __forceinline__ void cp16z(uint32_t dst, const void* src, uint32_t sz) {
    asm volatile("cp.async.cg.shared.global [%0], [%1], 16, %2;"
                 :: "r"(dst), "l"(src), "r"(sz));
}
__device__ __forceinline__ void cp_commit() {
    asm volatile("cp.async.commit_group;" ::: "memory");
}
template <int N>
__device__ __forceinline__ void cp_wait() {
    asm volatile("cp.async.wait_group %0;" :: "n"(N) : "memory");
}
__device__ __forceinline__ void ldsm4(uint32_t* r, uint32_t a) {
    asm volatile("ldmatrix.sync.aligned.m8n8.x4.shared.b16 {%0,%1,%2,%3}, [%4];"
                 : "=r"(r[0]), "=r"(r[1]), "=r"(r[2]), "=r"(r[3]) : "r"(a));
}
__device__ __forceinline__ void mma_bf16(float* d, const uint32_t* a, const uint32_t* b) {
    asm volatile(
        "mma.sync.aligned.m16n8k16.row.col.f32.bf16.bf16.f32 "
        "{%0,%1,%2,%3}, {%4,%5,%6,%7}, {%8,%9}, {%0,%1,%2,%3};"
        : "+f"(d[0]), "+f"(d[1]), "+f"(d[2]), "+f"(d[3])
        : "r"(a[0]), "r"(a[1]), "r"(a[2]), "r"(a[3]), "r"(b[0]), "r"(b[1]));
}
__device__ __forceinline__ float gelu_tanh(float x) {
    float x3 = x * x * x;
    return 0.5f * x * (1.0f + tanhf(0.7978845608028654f * (x + 0.044715f * x3)));
}
__device__ __forceinline__ void split_bf(float v, __nv_bfloat16& h, __nv_bfloat16& l) {
    h = __float2bfloat16(v);
    l = __float2bfloat16(v - __bfloat162float(h));
}

// ---------------- merged prep: a subset of weights in one kernel ---------
struct ConvAll {
    const float* src[12];
    __nv_bfloat16* hi[12];
    __nv_bfloat16* lo[12];
    int K[12], Nall[12], Kpad[12];
    int base[13];
};

__global__ void convert_all(ConvAll a)
{
    __shared__ float t[32][33];
    int bid = blockIdx.x;
    int w = 0;
    while (bid >= a.base[w + 1]) ++w;
    int local = bid - a.base[w];
    const int K = a.K[w], Nall = a.Nall[w], Kpad = a.Kpad[w];
    const int tilesY = (Nall + 31) >> 5;
    const int k0 = (local / tilesY) * 32, n0 = (local % tilesY) * 32;
    const float* W = a.src[w];
    __nv_bfloat16* Hi = a.hi[w];
    __nv_bfloat16* Lo = a.lo[w];

    for (int i = threadIdx.y; i < 32; i += 8) {
        int k = k0 + i, n = n0 + threadIdx.x;
        t[i][threadIdx.x] = (k < K && n < Nall) ? W[(size_t)k * Nall + n] : 0.f;
    }
    __syncthreads();
    for (int i = threadIdx.y; i < 32; i += 8) {
        int n = n0 + i, k = k0 + threadIdx.x;
        if (n < Nall && k < Kpad) {
            __nv_bfloat16 h, l; split_bf(t[threadIdx.x][i], h, l);
            Hi[(size_t)n * Kpad + k] = h;
            Lo[(size_t)n * Kpad + k] = l;
        }
    }
}

// ---------------- prep: x_bsd [64][720][64] -> xT hi/lo [4096][768] ------
__global__ void convert_x(const float* __restrict__ X,
                          __nv_bfloat16* __restrict__ Hi, __nv_bfloat16* __restrict__ Lo)
{
    __shared__ float t[32][33];
    int l0 = blockIdx.x * 32, c0 = blockIdx.y * 32, b = blockIdx.z;
    for (int i = threadIdx.y; i < 32; i += 8) {
        int l = l0 + i;
        t[i][threadIdx.x] = (l < L_) ? X[((size_t)b * L_ + l) * C_ + c0 + threadIdx.x] : 0.f;
    }
    __syncthreads();
    for (int i = threadIdx.y; i < 32; i += 8) {
        int c = c0 + i, l = l0 + threadIdx.x;
        __nv_bfloat16 h, lo; split_bf(t[threadIdx.x][i], h, lo);
        size_t o = (size_t)(b * 64 + c) * KPX + l;
        Hi[o] = h; Lo[o] = lo;
    }
}

// -- fused mma.sync GEMM: 64x128 tile, 8 warps (32x32), 3-deep k32 pipeline,
//    3 CTAs/SM.  Chunk (24KB): Ah 4K | Al 4K | Bh 8K | Bl 8K.
enum { EP_GELU = 0, EP_TANHPI = 1, EP_AFF = 2, EP_FINAL = 3 };

template <int EPI>
__global__ __launch_bounds__(256, 3)
void gemm_mma(const __nv_bfloat16* __restrict__ AH, const __nv_bfloat16* __restrict__ AL,
              int ldA, int KC32,
              const __nv_bfloat16* __restrict__ WH, const __nv_bfloat16* __restrict__ WL,
              int ldW, int Nlog,
              const float* __restrict__ VinF,
              const __nv_bfloat16* __restrict__ VinH, const __nv_bfloat16* __restrict__ VinL,
              int ldV, float vscale,
              const float* __restrict__ Theta,
              const float* __restrict__ Ay, const float* __restrict__ By,
              __nv_bfloat16* __restrict__ OutH, __nv_bfloat16* __restrict__ OutL,
              float* __restrict__ OutF, int ldO, int mbase)
{
    constexpr bool PAIR = (EPI == EP_AFF || EPI == EP_FINAL);
    constexpr int BN = 64;
    constexpr int RB = 128;
    constexpr int CH = 24576;

    extern __shared__ __align__(16) char smraw[];
    const uint32_t sbRaw = smem_u32(smraw);
    const uint32_t abU   = (sbRaw + 1023u) & ~1023u;
    char* ab = smraw + (abU - sbRaw);

    const int tid = threadIdx.x, wid = tid >> 5, lane = tid & 31;
    const int m0 = blockIdx.x * 64;
    const int n0 = blockIdx.y * (PAIR ? BN : RB);

    const int wm = wid >> 2, wn = wid & 3;
    float acc[2][4][4];
#pragma unroll
    for (int a = 0; a < 2; ++a)
#pragma unroll
        for (int b = 0; b < 4; ++b)
#pragma unroll
            for (int c = 0; c < 4; ++c) acc[a][b][c] = 0.f;

    uint32_t aoff[2], axr[2], boff[2], bxr[2];
#pragma unroll
    for (int t = 0; t < 2; ++t) {
        int r = wm * 32 + t * 16 + (lane & 15);
        uint32_t line = (uint32_t)((r & 31) * 128 + ((r >> 5) << 6));
        axr[t] = (line >> 3) & 0x70;
        aoff[t] = line;
    }
#pragma unroll
    for (int t = 0; t < 2; ++t) {
        int r = wn * 32 + ((lane >> 4) & 1) * 8 + (lane & 7) + t * 16;
        uint32_t line = (uint32_t)((r & 63) * 128 + ((r >> 6) << 6));
        bxr[t] = (line >> 3) & 0x70;
        boff[t] = line;
    }
    const uint32_t akb = ((lane >> 4) & 1) * 16;
    const uint32_t bkb = ((lane >> 3) & 1) * 16;

    auto issue_chunk = [&](int c) {
        const uint32_t ub = abU + (uint32_t)(c % 3) * CH;
        {
            int r = tid >> 2, q = tid & 3;
            uint32_t off = (uint32_t)((r & 31) * 128 + ((r >> 5) << 6));
            uint32_t so = (off + q * 16) ^ ((off >> 3) & 0x70);
            size_t go = (size_t)(m0 + r) * ldA + c * 32 + q * 8;
            cp16(ub + so,        AH + go);
            cp16(ub + 4096 + so, AL + go);
        }
#pragma unroll
        for (int i = 0; i < 2; ++i) {
            int idx = tid + i * 256;
            int r = idx >> 2, q = idx & 3;
            int wr, ok;
            if (PAIR) {
                if (r < BN) { int j = n0 + r;      ok = j < Nlog; wr = j; }
                else        { int j = n0 + r - BN; ok = j < Nlog; wr = Nlog + j; }
            } else { wr = n0 + r; ok = wr < Nlog; }
            int wrc = ok ? wr : 0;
            uint32_t sz = ok ? 16u : 0u;
            uint32_t off = (uint32_t)((r & 63) * 128 + ((r >> 6) << 6));
            uint32_t so = (off + q * 16) ^ ((off >> 3) & 0x70);
            size_t go = (size_t)wrc * ldW + c * 32 + q * 8;
            cp16z(ub + 8192 + so,  WH + go, sz);
            cp16z(ub + 16384 + so, WL + go, sz);
        }
        cp_commit();
    };

    auto compute = [&](int c) {
        const uint32_t uA  = abU + (uint32_t)(c % 3) * CH;
        const uint32_t uAl = uA + 4096, uB = uA + 8192, uBl = uA + 16384;
#pragma unroll
        for (int ks = 0; ks < 2; ++ks) {
            const uint32_t ka = ks * 32 + akb;
            const uint32_t kb = ks * 32 + bkb;
            uint32_t ah[2][4], al[2][4], bh[2][4], bl[2][4];
            ldsm4(ah[0], uA  + ((aoff[0] + ka) ^ axr[0]));
            ldsm4(ah[1], uA  + ((aoff[1] + ka) ^ axr[1]));
            ldsm4(bh[0], uB  + ((boff[0] + kb) ^ bxr[0]));
            ldsm4(bh[1], uB  + ((boff[1] + kb) ^ bxr[1]));
            ldsm4(al[0], uAl + ((aoff[0] + ka) ^ axr[0]));
            ldsm4(al[1], uAl + ((aoff[1] + ka) ^ axr[1]));
            ldsm4(bl[0], uBl + ((boff[0] + kb) ^ bxr[0]));
            ldsm4(bl[1], uBl + ((boff[1] + kb) ^ bxr[1]));
#pragma unroll
            for (int mt = 0; mt < 2; ++mt)
#pragma unroll
                for (int nt = 0; nt < 4; ++nt)
                    mma_bf16(acc[mt][nt], ah[mt], &bh[nt >> 1][(nt & 1) * 2]);
#pragma unroll
            for (int mt = 0; mt < 2; ++mt)
#pragma unroll
                for (int nt = 0; nt < 4; ++nt)
                    mma_bf16(acc[mt][nt], al[mt], &bh[nt >> 1][(nt & 1) * 2]);
#pragma unroll
            for (int mt = 0; mt < 2; ++mt)
#pragma unroll
                for (int nt = 0; nt < 4; ++nt)
                    mma_bf16(acc[mt][nt], ah[mt], &bl[nt >> 1][(nt & 1) * 2]);
        }
    };

    issue_chunk(0);
    if (KC32 > 1) issue_chunk(1);
#pragma unroll 1
    for (int c = 0; c < KC32; ++c) {
        if (c + 1 < KC32) cp_wait<1>(); else cp_wait<0>();
        __syncthreads();
        if (c + 2 < KC32) issue_chunk(c + 2);
        compute(c);
    }
    __syncthreads();

    constexpr int PITCH = 132;
    float* sAcc = reinterpret_cast<float*>(ab);
    {
        const int tr = lane >> 2, tc = (lane & 3) * 2;
#pragma unroll
        for (int mt = 0; mt < 2; ++mt)
#pragma unroll
            for (int nt = 0; nt < 4; ++nt) {
                int row = wm * 32 + mt * 16 + tr, col = wn * 32 + nt * 8 + tc;
                *reinterpret_cast<float2*>(&sAcc[row * PITCH + col]) =
                    make_float2(acc[mt][nt][0], acc[mt][nt][1]);
                *reinterpret_cast<float2*>(&sAcc[(row + 8) * PITCH + col]) =
                    make_float2(acc[mt][nt][2], acc[mt][nt][3]);
            }
    }
    __syncthreads();

    if (EPI == EP_GELU || EPI == EP_TANHPI) {
        for (int r = wid; r < 64; r += 8) {
            size_t ro = (size_t)(m0 + r) * ldO;
            for (int c = lane; c < RB; c += 32) {
                if (n0 + c >= Nlog) break;
                float a0 = sAcc[r * PITCH + c];
                float v = (EPI == EP_GELU) ? gelu_tanh(a0) : CUDART_PI_F * tanhf(a0);
                if (OutF) OutF[ro + n0 + c] = v;
                else { __nv_bfloat16 h, l; split_bf(v, h, l);
                       OutH[ro + n0 + c] = h; OutL[ro + n0 + c] = l; }
            }
        }
    } else if (EPI == EP_AFF) {
        for (int r = wid; r < 64; r += 8) {
            size_t rv = (size_t)(m0 + r) * ldV, ro = (size_t)(m0 + r) * ldO;
            for (int c = lane; c < BN; c += 32) {
                int n = n0 + c;
                if (n >= Nlog) break;
                float vin = VinF ? VinF[rv + n] * vscale
                                 : __bfloat162float(VinH[rv + n]) +
                                   __bfloat162float(VinL[rv + n]);
                float a0 = sAcc[r * PITCH + c], t0 = sAcc[r * PITCH + BN + c];
                float v = vin * __expf(tanhf(a0)) + t0;
                if (OutF) OutF[ro + n] = v;
                else { __nv_bfloat16 h, l; split_bf(v, h, l);
                       OutH[ro + n] = h; OutL[ro + n] = l; }
            }
        }
    } else { // EP_FINAL
        for (int r = wid; r < 64; r += 8) {
            int gm = m0 + r;
            int gmab = mbase + gm;
            int cch = gmab & 63, bb = gmab >> 6;
            size_t rv = (size_t)gm * ldV;
            for (int cp = lane; cp < BN / 2; cp += 32) {
                int j = cp * 2, n = n0 + j;
                if (n >= Nlog) break;
                int p = n >> 1;
                float a0 = sAcc[r * PITCH + j],      a1 = sAcc[r * PITCH + j + 1];
                float t0 = sAcc[r * PITCH + BN + j], t1 = sAcc[r * PITCH + BN + j + 1];
                float th = Theta[(size_t)gm * P2_ + p], sn, cs;
                sincosf(th, &sn, &cs);
                float av = Ay[cch * P2_ + p], bv = By[cch * P2_ + p];
                float rn = rsqrtf(av * av + bv * bv);
                float ca = av * rn, cb = bv * rn;
                float2 yv = *reinterpret_cast<const float2*>(VinF + rv + n);
                float r1 = cs * yv.x - sn * yv.y, i1 = sn * yv.x + cs * yv.y;
                float r2 = ca * r1 - cb * i1, i2 = cb * r1 + ca * i1;
                float r3 = r2 * __expf(tanhf(a0)), i3 = i2 * __expf(tanhf(a1));
                float r4 = ca * r3 + cb * i3,  i4 = -cb * r3 + ca * i3;
                float r5 = cs * r4 + sn * i4,  i5 = -sn * r4 + cs * i4;
                OutF[((size_t)bb * P_ + n) * C_ + cch]     = r5 + t0;
                OutF[((size_t)bb * P_ + n + 1) * C_ + cch] = i5 + t1;
            }
        }
    }
}

// ---------------- host ----------------
constexpr int SMEMSZ = 3 * 24576 + 1024;

extern "C" void kernel_launch(void* const* d_in, const int* in_sizes, int n_in,
                              void* d_out, int out_size)
{
    (void)in_sizes; (void)n_in; (void)out_size;
    const float* x_bsd = (const float*)d_in[0];
    const float* z0    = (const float*)d_in[1];
    const float* y0    = (const float*)d_in[2];
    const float* a_y   = (const float*)d_in[16];
    const float* b_y   = (const float*)d_in[17];
    float* out = (float*)d_out;

    __nv_bfloat16 *wph, *wpl, *xh, *xl, *hh, *hl, *zh, *zl;
    float *y, *th;
    cudaGetSymbolAddress((void**)&wph, g_wph);
    cudaGetSymbolAddress((void**)&wpl, g_wpl);
    cudaGetSymbolAddress((void**)&xh, g_xh);  cudaGetSymbolAddress((void**)&xl, g_xl);
    cudaGetSymbolAddress((void**)&hh, g_hh);  cudaGetSymbolAddress((void**)&hl, g_hl);
    cudaGetSymbolAddress((void**)&zh, g_zh);  cudaGetSymbolAddress((void**)&zl, g_zl);
    cudaGetSymbolAddress((void**)&y,  g_y);   cudaGetSymbolAddress((void**)&th, g_th);

    static cudaStream_t s2 = nullptr, s3 = nullptr;
    static cudaEvent_t evStart = nullptr, evX = nullptr, evWh = nullptr,
                       evRest = nullptr, evC1 = nullptr;
    static bool attr_done = false;
    if (!attr_done) {
        cudaFuncSetAttribute(gemm_mma<EP_GELU>,   cudaFuncAttributeMaxDynamicSharedMemorySize, SMEMSZ);
        cudaFuncSetAttribute(gemm_mma<EP_TANHPI>, cudaFuncAttributeMaxDynamicSharedMemorySize, SMEMSZ);
        cudaFuncSetAttribute(gemm_mma<EP_AFF>,    cudaFuncAttributeMaxDynamicSharedMemorySize, SMEMSZ);
        cudaFuncSetAttribute(gemm_mma<EP_FINAL>,  cudaFuncAttributeMaxDynamicSharedMemorySize, SMEMSZ);
        cudaStreamCreateWithFlags(&s2, cudaStreamNonBlocking);
        cudaStreamCreateWithFlags(&s3, cudaStreamNonBlocking);
        cudaEventCreateWithFlags(&evStart, cudaEventDisableTiming);
        cudaEventCreateWithFlags(&evX,     cudaEventDisableTiming);
        cudaEventCreateWithFlags(&evWh,    cudaEventDisableTiming);
        cudaEventCreateWithFlags(&evRest,  cudaEventDisableTiming);
        cudaEventCreateWithFlags(&evC1,    cudaEventDisableTiming);
        attr_done = true;
    }

    struct WS { int idx; int K, Nall, Kpad; size_t off; };
    const WS ws[12] = {
        {3, 720, 512, 768, OFF_WH},  {4, 512, 1024, 512, OFF_SSZ},
        {5, 720, 1024, 768, OFF_XZ2},{6, 720, 1024, 768, OFF_XZ3},
        {7, 720, 1024, 768, OFF_XZ4},{8, 720, 1024, 768, OFF_XZ5},
        {9, 512, 1440, 512, OFF_ZX0},{10,512, 1440, 512, OFF_ZX2},
        {11,512, 1440, 512, OFF_ZX3},{13,512, 672,  512, OFF_ZY},
        {14,512, 168,  512, OFF_ROT},{15,512, 672,  512, OFF_KOO},
    };
    ConvAll cwh; ConvAll crest;
    cwh.src[0]  = (const float*)d_in[ws[0].idx];
    cwh.hi[0]   = wph + ws[0].off; cwh.lo[0] = wpl + ws[0].off;
    cwh.K[0] = ws[0].K; cwh.Nall[0] = ws[0].Nall; cwh.Kpad[0] = ws[0].Kpad;
    int t0 = (ws[0].Kpad / 32) * ((ws[0].Nall + 31) / 32);
    cwh.base[0] = 0;
    for (int j = 1; j <= 12; ++j) cwh.base[j] = t0;
    int total = 0;
    for (int i = 1; i < 12; ++i) {
        int k = i - 1;
        crest.src[k]  = (const float*)d_in[ws[i].idx];
        crest.hi[k]   = wph + ws[i].off; crest.lo[k] = wpl + ws[i].off;
        crest.K[k] = ws[i].K; crest.Nall[k] = ws[i].Nall; crest.Kpad[k] = ws[i].Kpad;
        crest.base[k] = total;
        total += (ws[i].Kpad / 32) * ((ws[i].Nall + 31) / 32);
    }
    for (int j = 11; j <= 12; ++j) crest.base[j] = total;

    const __nv_bfloat16* Z = nullptr; const float* ZF = nullptr;

    // ---- prep: weights on s2, x-transpose on main ----
    cudaEventRecord(evStart, 0);
    cudaStreamWaitEvent(s2, evStart, 0);
    convert_all<<<cwh.base[1], dim3(32, 8), 0, s2>>>(cwh);
    cudaEventRecord(evWh, s2);
    convert_all<<<total, dim3(32, 8), 0, s2>>>(crest);
    cudaEventRecord(evRest, s2);

    convert_x<<<dim3(24, 2, 64), dim3(32, 8), 0, 0>>>(x_bsd, xh, xl);
    cudaEventRecord(evX, 0);

    // ---- two half-M chains (rows [0,2048) on main, [2048,4096) on s3) ----
    auto chain = [&](cudaStream_t st, int R) {
        size_t rx = (size_t)R * 768, rz = (size_t)R * 512;
        size_t ry = (size_t)R * P_, rt = (size_t)R * P2_;
        // h = gelu(xT @ W_h)
        gemm_mma<EP_GELU><<<dim3(32, 4), 256, SMEMSZ, st>>>(
            xh + rx, xl + rx, 768, 23, wph + OFF_WH, wpl + OFF_WH, 768, 512,
            ZF, Z, Z, 0, 0.f, ZF, ZF, ZF, hh + rz, hl + rz, nullptr, 512, 0);
        cudaStreamWaitEvent(st, evRest, 0);
        // z1 = affine(0.1*z0 ; h @ W_ssz)
        gemm_mma<EP_AFF><<<dim3(32, 8), 256, SMEMSZ, st>>>(
            hh + rz, hl + rz, 512, 16, wph + OFF_SSZ, wpl + OFF_SSZ, 512, 512,
            z0 + rz, Z, Z, 512, 0.1f, ZF, ZF, ZF, zh + rz, zl + rz, nullptr, 512, 0);
        // x1 = affine(xT ; z1 @ W_zx_v0)
        gemm_mma<EP_AFF><<<dim3(32, 12), 256, SMEMSZ, st>>>(
            zh + rz, zl + rz, 512, 16, wph + OFF_ZX0, wpl + OFF_ZX0, 512, 720,
            ZF, xh + rx, xl + rx, 768, 1.f, ZF, ZF, ZF, xh + rx, xl + rx, nullptr, 768, 0);
        // z2 = affine(z1 ; x1 @ W_xz_v2)
        gemm_mma<EP_AFF><<<dim3(32, 8), 256, SMEMSZ, st>>>(
            xh + rx, xl + rx, 768, 23, wph + OFF_XZ2, wpl + OFF_XZ2, 768, 512,
            ZF, zh + rz, zl + rz, 512, 1.f, ZF, ZF, ZF, zh + rz, zl + rz, nullptr, 512, 0);
        // x2 = affine(x1 ; z2 @ W_zx_v2)
        gemm_mma<EP_AFF><<<dim3(32, 12), 256, SMEMSZ, st>>>(
            zh + rz, zl + rz, 512, 16, wph + OFF_ZX2, wpl + OFF_ZX2, 512, 720,
            ZF, xh + rx, xl + rx, 768, 1.f, ZF, ZF, ZF, xh + rx, xl + rx, nullptr, 768, 0);
        // z3 = affine(z2 ; x2 @ W_xz_v3)
        gemm_mma<EP_AFF><<<dim3(32, 8), 256, SMEMSZ, st>>>(
            xh + rx, xl + rx, 768, 23, wph + OFF_XZ3, wpl + OFF_XZ3, 768, 512,
            ZF, zh + rz, zl + rz, 512, 1.f, ZF, ZF, ZF, zh + rz, zl + rz, nullptr, 512, 0);
        // x3 = affine(x2 ; z3 @ W_zx_v3)
        gemm_mma<EP_AFF><<<dim3(32, 12), 256, SMEMSZ, st>>>(
            zh + rz, zl + rz, 512, 16, wph + OFF_ZX3, wpl + OFF_ZX3, 512, 720,
            ZF, xh + rx, xl + rx, 768, 1.f, ZF, ZF, ZF, xh + rx, xl + rx, nullptr, 768, 0);
        // z4 = affine(z3 ; x3 @ W_xz_v4)
        gemm_mma<EP_AFF><<<dim3(32, 8), 256, SMEMSZ, st>>>(
            xh + rx, xl + rx, 768, 23, wph + OFF_XZ4, wpl + OFF_XZ4, 768, 512,
            ZF, zh + rz, zl + rz, 512, 1.f, ZF, ZF, ZF, zh + rz, zl + rz, nullptr, 512, 0);
        // y = affine(0.1*y0 ; z4 @ W_zy_v4)
        gemm_mma<EP_AFF><<<dim3(32, 6), 256, SMEMSZ, st>>>(
            zh + rz, zl + rz, 512, 16, wph + OFF_ZY, wpl + OFF_ZY, 512, 336,
            y0 + ry, Z, Z, 336, 0.1f, ZF, ZF, ZF, nullptr, nullptr, y + ry, 336, 0);
        // z5 = affine(z4 ; x3 @ W_xz_v5) -> hh/hl
        gemm_mma<EP_AFF><<<dim3(32, 8), 256, SMEMSZ, st>>>(
            xh + rx, xl + rx, 768, 23, wph + OFF_XZ5, wpl + OFF_XZ5, 768, 512,
            ZF, zh + rz, zl + rz, 512, 1.f, ZF, ZF, ZF, hh + rz, hl + rz, nullptr, 512, 0);
        // theta = pi*tanh(z5 @ W_rot)
        gemm_mma<EP_TANHPI><<<dim3(32, 2), 256, SMEMSZ, st>>>(
            hh + rz, hl + rz, 512, 16, wph + OFF_ROT, wpl + OFF_ROT, 512, 168,
            ZF, Z, Z, 0, 0.f, ZF, ZF, ZF, nullptr, nullptr, th + rt, 168, 0);
        // final
        gemm_mma<EP_FINAL><<<dim3(32, 6), 256, SMEMSZ, st>>>(
            hh + rz, hl + rz, 512, 16, wph + OFF_KOO, wpl + OFF_KOO, 512, 336,
            y + ry, Z, Z, 336, 1.f, th + rt, a_y, b_y, nullptr, nullptr, out, 0, R);
    };

    // chain1 on s3 (waits for x-transpose and W_h)
    cudaStreamWaitEvent(s3, evX, 0);
    cudaStreamWaitEvent(s3, evWh, 0);
    chain(s3, 2048);
    cudaEventRecord(evC1, s3);

    // chain0 on main (convert_x already ordered on main; wait W_h)
    cudaStreamWaitEvent(0, evWh, 0);
    chain(0, 0);

    cudaStreamWaitEvent(0, evC1, 0);
}

// round 17
// speedup vs baseline: 1.7075x; 1.0352x over previous
#include <cuda_runtime.h>
#include <cuda_bf16.h>
#include <math_constants.h>
#include <cstdint>

// ---------------- problem constants ----------------
constexpr int C_  = 64;
constexpr int L_  = 720;
constexpr int P_  = 336;
constexpr int P2_ = 168;
constexpr int M_  = 4096;   // B*C
constexpr int KPX = 768;    // 720 padded to 64

// ---------------- weight pool offsets (transposed [Nall][Kpad] bf16) -----
constexpr size_t OFF_WH  = 0;                 constexpr size_t SZ_WH  = 512  * 768;
constexpr size_t OFF_SSZ = OFF_WH  + SZ_WH;   constexpr size_t SZ_SSZ = 1024 * 512;
constexpr size_t OFF_XZ2 = OFF_SSZ + SZ_SSZ;  constexpr size_t SZ_XZ  = 1024 * 768;
constexpr size_t OFF_XZ3 = OFF_XZ2 + SZ_XZ;
constexpr size_t OFF_XZ4 = OFF_XZ3 + SZ_XZ;
constexpr size_t OFF_XZ5 = OFF_XZ4 + SZ_XZ;
constexpr size_t OFF_ZX0 = OFF_XZ5 + SZ_XZ;   constexpr size_t SZ_ZX  = 1440 * 512;
constexpr size_t OFF_ZX2 = OFF_ZX0 + SZ_ZX;
constexpr size_t OFF_ZX3 = OFF_ZX2 + SZ_ZX;
constexpr size_t OFF_ZY  = OFF_ZX3 + SZ_ZX;   constexpr size_t SZ_ZY  = 672 * 512;
constexpr size_t OFF_ROT = OFF_ZY  + SZ_ZY;   constexpr size_t SZ_ROT = 168 * 512;
constexpr size_t OFF_KOO = OFF_ROT + SZ_ROT;  constexpr size_t SZ_KOO = 672 * 512;
constexpr size_t POOL    = OFF_KOO + SZ_KOO;

// ---------------- static device scratch ----------------
__device__ __align__(128) __nv_bfloat16 g_wph[POOL];
__device__ __align__(128) __nv_bfloat16 g_wpl[POOL];
__device__ __align__(128) __nv_bfloat16 g_xh[M_ * KPX], g_xl[M_ * KPX];
__device__ __align__(128) __nv_bfloat16 g_hh[M_ * 512], g_hl[M_ * 512];
__device__ __align__(128) __nv_bfloat16 g_zh[M_ * 512], g_zl[M_ * 512];
__device__ __align__(128) float g_y [M_ * P_];
__device__ __align__(128) float g_th[M_ * P2_];

// ---------------- helpers ----------------
__device__ __forceinline__ uint32_t smem_u32(const void* p) {
    uint32_t a;
    asm("{ .reg .u64 t; cvta.to.shared.u64 t, %1; cvt.u32.u64 %0, t; }" : "=r"(a) : "l"(p));
    return a;
}
__device__ __forceinline__ void cp16(uint32_t dst, const void* src) {
    asm volatile("cp.async.cg.shared.global [%0], [%1], 16;" :: "r"(dst), "l"(src));
}
__device__ __forceinline__ void cp16z(uint32_t dst, const void* src, uint32_t sz) {
    asm volatile("cp.async.cg.shared.global [%0], [%1], 16, %2;"
                 :: "r"(dst), "l"(src), "r"(sz));
}
__device__ __forceinline__ void cp_commit() {
    asm volatile("cp.async.commit_group;" ::: "memory");
}
template <int N>
__device__ __forceinline__ void cp_wait() {
    asm volatile("cp.async.wait_group %0;" :: "n"(N) : "memory");
}
__device__ __forceinline__ void ldsm4(uint32_t* r, uint32_t a) {
    asm volatile("ldmatrix.sync.aligned.m8n8.x4.shared.b16 {%0,%1,%2,%3}, [%4];"
                 : "=r"(r[0]), "=r"(r[1]), "=r"(r[2]), "=r"(r[3]) : "r"(a));
}
__device__ __forceinline__ void mma_bf16(float* d, const uint32_t* a, const uint32_t* b) {
    asm volatile(
        "mma.sync.aligned.m16n8k16.row.col.f32.bf16.bf16.f32 "
        "{%0,%1,%2,%3}, {%4,%5,%6,%7}, {%8,%9}, {%0,%1,%2,%3};"
        : "+f"(d[0]), "+f"(d[1]), "+f"(d[2]), "+f"(d[3])
        : "r"(a[0]), "r"(a[1]), "r"(a[2]), "r"(a[3]), "r"(b[0]), "r"(b[1]));
}
__device__ __forceinline__ float gelu_tanh(float x) {
    float x3 = x * x * x;
    return 0.5f * x * (1.0f + tanhf(0.7978845608028654f * (x + 0.044715f * x3)));
}
__device__ __forceinline__ void split_bf(float v, __nv_bfloat16& h, __nv_bfloat16& l) {
    h = __float2bfloat16(v);
    l = __float2bfloat16(v - __bfloat162float(h));
}

// ---------------- merged prep: a subset of weights in one kernel ---------
struct ConvAll {
    const float* src[12];
    __nv_bfloat16* hi[12];
    __nv_bfloat16* lo[12];
    int K[12], Nall[12], Kpad[12];
    int base[13];
};

__global__ void convert_all(ConvAll a)
{
    __shared__ float t[32][33];
    int bid = blockIdx.x;
    int w = 0;
    while (bid >= a.base[w + 1]) ++w;
    int local = bid - a.base[w];
    const int K = a.K[w], Nall = a.Nall[w], Kpad = a.Kpad[w];
    const int tilesY = (Nall + 31) >> 5;
    const int k0 = (local / tilesY) * 32, n0 = (local % tilesY) * 32;
    const float* W = a.src[w];
    __nv_bfloat16* Hi = a.hi[w];
    __nv_bfloat16* Lo = a.lo[w];

    for (int i = threadIdx.y; i < 32; i += 8) {
        int k = k0 + i, n = n0 + threadIdx.x;
        t[i][threadIdx.x] = (k < K && n < Nall) ? W[(size_t)k * Nall + n] : 0.f;
    }
    __syncthreads();
    for (int i = threadIdx.y; i < 32; i += 8) {
        int n = n0 + i, k = k0 + threadIdx.x;
        if (n < Nall && k < Kpad) {
            __nv_bfloat16 h, l; split_bf(t[threadIdx.x][i], h, l);
            Hi[(size_t)n * Kpad + k] = h;
            Lo[(size_t)n * Kpad + k] = l;
        }
    }
}

// ---------------- prep: x_bsd [64][720][64] -> xT hi/lo [4096][768] ------
__global__ void convert_x(const float* __restrict__ X,
                          __nv_bfloat16* __restrict__ Hi, __nv_bfloat16* __restrict__ Lo)
{
    __shared__ float t[32][33];
    int l0 = blockIdx.x * 32, c0 = blockIdx.y * 32, b = blockIdx.z;
    for (int i = threadIdx.y; i < 32; i += 8) {
        int l = l0 + i;
        t[i][threadIdx.x] = (l < L_) ? X[((size_t)b * L_ + l) * C_ + c0 + threadIdx.x] : 0.f;
    }
    __syncthreads();
    for (int i = threadIdx.y; i < 32; i += 8) {
        int c = c0 + i, l = l0 + threadIdx.x;
        __nv_bfloat16 h, lo; split_bf(t[threadIdx.x][i], h, lo);
        size_t o = (size_t)(b * 64 + c) * KPX + l;
        Hi[o] = h; Lo[o] = lo;
    }
}

// -- fused mma.sync GEMM: 64x128 tile, 8 warps (32x32), 3-deep k32 pipeline,
//    3 CTAs/SM.  Chunk (24KB): Ah 4K | Al 4K | Bh 8K | Bl 8K.
enum { EP_GELU = 0, EP_TANHPI = 1, EP_AFF = 2, EP_FINAL = 3 };

template <int EPI>
__global__ __launch_bounds__(256, 3)
void gemm_mma(const __nv_bfloat16* __restrict__ AH, const __nv_bfloat16* __restrict__ AL,
              int ldA, int KC32,
              const __nv_bfloat16* __restrict__ WH, const __nv_bfloat16* __restrict__ WL,
              int ldW, int Nlog,
              const float* __restrict__ VinF,
              const __nv_bfloat16* __restrict__ VinH, const __nv_bfloat16* __restrict__ VinL,
              int ldV, float vscale,
              const float* __restrict__ Theta,
              const float* __restrict__ Ay, const float* __restrict__ By,
              __nv_bfloat16* __restrict__ OutH, __nv_bfloat16* __restrict__ OutL,
              float* __restrict__ OutF, int ldO, int mbase)
{
    constexpr bool PAIR = (EPI == EP_AFF || EPI == EP_FINAL);
    constexpr int BN = 64;
    constexpr int RB = 128;
    constexpr int CH = 24576;

    extern __shared__ __align__(16) char smraw[];
    const uint32_t sbRaw = smem_u32(smraw);
    const uint32_t abU   = (sbRaw + 1023u) & ~1023u;
    char* ab = smraw + (abU - sbRaw);

    const int tid = threadIdx.x, wid = tid >> 5, lane = tid & 31;
    const int m0 = blockIdx.x * 64;
    const int n0 = blockIdx.y * (PAIR ? BN : RB);

    const int wm = wid >> 2, wn = wid & 3;
    float acc[2][4][4];
#pragma unroll
    for (int a = 0; a < 2; ++a)
#pragma unroll
        for (int b = 0; b < 4; ++b)
#pragma unroll
            for (int c = 0; c < 4; ++c) acc[a][b][c] = 0.f;

    uint32_t aoff[2], axr[2], boff[2], bxr[2];
#pragma unroll
    for (int t = 0; t < 2; ++t) {
        int r = wm * 32 + t * 16 + (lane & 15);
        uint32_t line = (uint32_t)((r & 31) * 128 + ((r >> 5) << 6));
        axr[t] = (line >> 3) & 0x70;
        aoff[t] = line;
    }
#pragma unroll
    for (int t = 0; t < 2; ++t) {
        int r = wn * 32 + ((lane >> 4) & 1) * 8 + (lane & 7) + t * 16;
        uint32_t line = (uint32_t)((r & 63) * 128 + ((r >> 6) << 6));
        bxr[t] = (line >> 3) & 0x70;
        boff[t] = line;
    }
    const uint32_t akb = ((lane >> 4) & 1) * 16;
    const uint32_t bkb = ((lane >> 3) & 1) * 16;

    auto issue_chunk = [&](int c) {
        const uint32_t ub = abU + (uint32_t)(c % 3) * CH;
        {
            int r = tid >> 2, q = tid & 3;
            uint32_t off = (uint32_t)((r & 31) * 128 + ((r >> 5) << 6));
            uint32_t so = (off + q * 16) ^ ((off >> 3) & 0x70);
            size_t go = (size_t)(m0 + r) * ldA + c * 32 + q * 8;
            cp16(ub + so,        AH + go);
            cp16(ub + 4096 + so, AL + go);
        }
#pragma unroll
        for (int i = 0; i < 2; ++i) {
            int idx = tid + i * 256;
            int r = idx >> 2, q = idx & 3;
            int wr, ok;
            if (PAIR) {
                if (r < BN) { int j = n0 + r;      ok = j < Nlog; wr = j; }
                else        { int j = n0 + r - BN; ok = j < Nlog; wr = Nlog + j; }
            } else { wr = n0 + r; ok = wr < Nlog; }
            int wrc = ok ? wr : 0;
            uint32_t sz = ok ? 16u : 0u;
            uint32_t off = (uint32_t)((r & 63) * 128 + ((r >> 6) << 6));
            uint32_t so = (off + q * 16) ^ ((off >> 3) & 0x70);
            size_t go = (size_t)wrc * ldW + c * 32 + q * 8;
            cp16z(ub + 8192 + so,  WH + go, sz);
            cp16z(ub + 16384 + so, WL + go, sz);
        }
        cp_commit();
    };

    auto compute = [&](int c) {
        const uint32_t uA  = abU + (uint32_t)(c % 3) * CH;
        const uint32_t uAl = uA + 4096, uB = uA + 8192, uBl = uA + 16384;
#pragma unroll
        for (int ks = 0; ks < 2; ++ks) {
            const uint32_t ka = ks * 32 + akb;
            const uint32_t kb = ks * 32 + bkb;
            uint32_t ah[2][4], al[2][4], bh[2][4], bl[2][4];
            ldsm4(ah[0], uA  + ((aoff[0] + ka) ^ axr[0]));
            ldsm4(ah[1], uA  + ((aoff[1] + ka) ^ axr[1]));
            ldsm4(bh[0], uB  + ((boff[0] + kb) ^ bxr[0]));
            ldsm4(bh[1], uB  + ((boff[1] + kb) ^ bxr[1]));
            ldsm4(al[0], uAl + ((aoff[0] + ka) ^ axr[0]));
            ldsm4(al[1], uAl + ((aoff[1] + ka) ^ axr[1]));
            ldsm4(bl[0], uBl + ((boff[0] + kb) ^ bxr[0]));
            ldsm4(bl[1], uBl + ((boff[1] + kb) ^ bxr[1]));
#pragma unroll
            for (int mt = 0; mt < 2; ++mt)
#pragma unroll
                for (int nt = 0; nt < 4; ++nt)
                    mma_bf16(acc[mt][nt], ah[mt], &bh[nt >> 1][(nt & 1) * 2]);
#pragma unroll
            for (int mt = 0; mt < 2; ++mt)
#pragma unroll
                for (int nt = 0; nt < 4; ++nt)
                    mma_bf16(acc[mt][nt], al[mt], &bh[nt >> 1][(nt & 1) * 2]);
#pragma unroll
            for (int mt = 0; mt < 2; ++mt)
#pragma unroll
                for (int nt = 0; nt < 4; ++nt)
                    mma_bf16(acc[mt][nt], ah[mt], &bl[nt >> 1][(nt & 1) * 2]);
        }
    };

    issue_chunk(0);
    if (KC32 > 1) issue_chunk(1);
#pragma unroll 1
    for (int c = 0; c < KC32; ++c) {
        if (c + 1 < KC32) cp_wait<1>(); else cp_wait<0>();
        __syncthreads();
        if (c + 2 < KC32) issue_chunk(c + 2);
        compute(c);
    }
    __syncthreads();

    constexpr int PITCH = 132;
    float* sAcc = reinterpret_cast<float*>(ab);
    {
        const int tr = lane >> 2, tc = (lane & 3) * 2;
#pragma unroll
        for (int mt = 0; mt < 2; ++mt)
#pragma unroll
            for (int nt = 0; nt < 4; ++nt) {
                int row = wm * 32 + mt * 16 + tr, col = wn * 32 + nt * 8 + tc;
                *reinterpret_cast<float2*>(&sAcc[row * PITCH + col]) =
                    make_float2(acc[mt][nt][0], acc[mt][nt][1]);
                *reinterpret_cast<float2*>(&sAcc[(row + 8) * PITCH + col]) =
                    make_float2(acc[mt][nt][2], acc[mt][nt][3]);
            }
    }
    __syncthreads();

    if (EPI == EP_GELU || EPI == EP_TANHPI) {
        for (int r = wid; r < 64; r += 8) {
            size_t ro = (size_t)(m0 + r) * ldO;
            for (int c = lane; c < RB; c += 32) {
                if (n0 + c >= Nlog) break;
                float a0 = sAcc[r * PITCH + c];
                float v = (EPI == EP_GELU) ? gelu_tanh(a0) : CUDART_PI_F * tanhf(a0);
                if (OutF) OutF[ro + n0 + c] = v;
                else { __nv_bfloat16 h, l; split_bf(v, h, l);
                       OutH[ro + n0 + c] = h; OutL[ro + n0 + c] = l; }
            }
        }
    } else if (EPI == EP_AFF) {
        for (int r = wid; r < 64; r += 8) {
            size_t rv = (size_t)(m0 + r) * ldV, ro = (size_t)(m0 + r) * ldO;
            for (int c = lane; c < BN; c += 32) {
                int n = n0 + c;
                if (n >= Nlog) break;
                float vin = VinF ? VinF[rv + n] * vscale
                                 : __bfloat162float(VinH[rv + n]) +
                                   __bfloat162float(VinL[rv + n]);
                float a0 = sAcc[r * PITCH + c], t0 = sAcc[r * PITCH + BN + c];
                float v = vin * __expf(tanhf(a0)) + t0;
                if (OutF) OutF[ro + n] = v;
                else { __nv_bfloat16 h, l; split_bf(v, h, l);
                       OutH[ro + n] = h; OutL[ro + n] = l; }
            }
        }
    } else { // EP_FINAL
        for (int r = wid; r < 64; r += 8) {
            int gm = m0 + r;
            int gmab = mbase + gm;
            int cch = gmab & 63, bb = gmab >> 6;
            size_t rv = (size_t)gm * ldV;
            for (int cp = lane; cp < BN / 2; cp += 32) {
                int j = cp * 2, n = n0 + j;
                if (n >= Nlog) break;
                int p = n >> 1;
                float a0 = sAcc[r * PITCH + j],      a1 = sAcc[r * PITCH + j + 1];
                float t0 = sAcc[r * PITCH + BN + j], t1 = sAcc[r * PITCH + BN + j + 1];
                float th = Theta[(size_t)gm * P2_ + p], sn, cs;
                sincosf(th, &sn, &cs);
                float av = Ay[cch * P2_ + p], bv = By[cch * P2_ + p];
                float rn = rsqrtf(av * av + bv * bv);
                float ca = av * rn, cb = bv * rn;
                float2 yv = *reinterpret_cast<const float2*>(VinF + rv + n);
                float r1 = cs * yv.x - sn * yv.y, i1 = sn * yv.x + cs * yv.y;
                float r2 = ca * r1 - cb * i1, i2 = cb * r1 + ca * i1;
                float r3 = r2 * __expf(tanhf(a0)), i3 = i2 * __expf(tanhf(a1));
                float r4 = ca * r3 + cb * i3,  i4 = -cb * r3 + ca * i3;
                float r5 = cs * r4 + sn * i4,  i5 = -sn * r4 + cs * i4;
                OutF[((size_t)bb * P_ + n) * C_ + cch]     = r5 + t0;
                OutF[((size_t)bb * P_ + n + 1) * C_ + cch] = i5 + t1;
            }
        }
    }
}

// ---------------- host ----------------
constexpr int SMEMSZ = 3 * 24576 + 1024;
// 3 chains: rows [0,1344) [1344,2688) [2688,4096); same stream set as R15.
constexpr int CH_R[3]  = {0, 1344, 2688};
constexpr int CH_GX[3] = {21, 21, 22};

extern "C" void kernel_launch(void* const* d_in, const int* in_sizes, int n_in,
                              void* d_out, int out_size)
{
    (void)in_sizes; (void)n_in; (void)out_size;
    const float* x_bsd = (const float*)d_in[0];
    const float* z0    = (const float*)d_in[1];
    const float* y0    = (const float*)d_in[2];
    const float* a_y   = (const float*)d_in[16];
    const float* b_y   = (const float*)d_in[17];
    float* out = (float*)d_out;

    __nv_bfloat16 *wph, *wpl, *xh, *xl, *hh, *hl, *zh, *zl;
    float *y, *th;
    cudaGetSymbolAddress((void**)&wph, g_wph);
    cudaGetSymbolAddress((void**)&wpl, g_wpl);
    cudaGetSymbolAddress((void**)&xh, g_xh);  cudaGetSymbolAddress((void**)&xl, g_xl);
    cudaGetSymbolAddress((void**)&hh, g_hh);  cudaGetSymbolAddress((void**)&hl, g_hl);
    cudaGetSymbolAddress((void**)&zh, g_zh);  cudaGetSymbolAddress((void**)&zl, g_zl);
    cudaGetSymbolAddress((void**)&y,  g_y);   cudaGetSymbolAddress((void**)&th, g_th);

    static cudaStream_t s2 = nullptr, s3 = nullptr;
    static cudaEvent_t evStart = nullptr, evX = nullptr, evWh = nullptr,
                       evRest = nullptr, evC1 = nullptr, evC2 = nullptr;
    static bool attr_done = false;
    if (!attr_done) {
        cudaFuncSetAttribute(gemm_mma<EP_GELU>,   cudaFuncAttributeMaxDynamicSharedMemorySize, SMEMSZ);
        cudaFuncSetAttribute(gemm_mma<EP_TANHPI>, cudaFuncAttributeMaxDynamicSharedMemorySize, SMEMSZ);
        cudaFuncSetAttribute(gemm_mma<EP_AFF>,    cudaFuncAttributeMaxDynamicSharedMemorySize, SMEMSZ);
        cudaFuncSetAttribute(gemm_mma<EP_FINAL>,  cudaFuncAttributeMaxDynamicSharedMemorySize, SMEMSZ);
        cudaStreamCreateWithFlags(&s2, cudaStreamNonBlocking);
        cudaStreamCreateWithFlags(&s3, cudaStreamNonBlocking);
        cudaEventCreateWithFlags(&evStart, cudaEventDisableTiming);
        cudaEventCreateWithFlags(&evX,     cudaEventDisableTiming);
        cudaEventCreateWithFlags(&evWh,    cudaEventDisableTiming);
        cudaEventCreateWithFlags(&evRest,  cudaEventDisableTiming);
        cudaEventCreateWithFlags(&evC1,    cudaEventDisableTiming);
        cudaEventCreateWithFlags(&evC2,    cudaEventDisableTiming);
        attr_done = true;
    }

    struct WS { int idx; int K, Nall, Kpad; size_t off; };
    const WS ws[12] = {
        {3, 720, 512, 768, OFF_WH},  {4, 512, 1024, 512, OFF_SSZ},
        {5, 720, 1024, 768, OFF_XZ2},{6, 720, 1024, 768, OFF_XZ3},
        {7, 720, 1024, 768, OFF_XZ4},{8, 720, 1024, 768, OFF_XZ5},
        {9, 512, 1440, 512, OFF_ZX0},{10,512, 1440, 512, OFF_ZX2},
        {11,512, 1440, 512, OFF_ZX3},{13,512, 672,  512, OFF_ZY},
        {14,512, 168,  512, OFF_ROT},{15,512, 672,  512, OFF_KOO},
    };
    ConvAll cwh; ConvAll crest;
    cwh.src[0]  = (const float*)d_in[ws[0].idx];
    cwh.hi[0]   = wph + ws[0].off; cwh.lo[0] = wpl + ws[0].off;
    cwh.K[0] = ws[0].K; cwh.Nall[0] = ws[0].Nall; cwh.Kpad[0] = ws[0].Kpad;
    int t0 = (ws[0].Kpad / 32) * ((ws[0].Nall + 31) / 32);
    cwh.base[0] = 0;
    for (int j = 1; j <= 12; ++j) cwh.base[j] = t0;
    int total = 0;
    for (int i = 1; i < 12; ++i) {
        int k = i - 1;
        crest.src[k]  = (const float*)d_in[ws[i].idx];
        crest.hi[k]   = wph + ws[i].off; crest.lo[k] = wpl + ws[i].off;
        crest.K[k] = ws[i].K; crest.Nall[k] = ws[i].Nall; crest.Kpad[k] = ws[i].Kpad;
        crest.base[k] = total;
        total += (ws[i].Kpad / 32) * ((ws[i].Nall + 31) / 32);
    }
    for (int j = 11; j <= 12; ++j) crest.base[j] = total;

    const __nv_bfloat16* Z = nullptr; const float* ZF = nullptr;

    // ---- prep: weights on s2, x-transpose on main ----
    cudaEventRecord(evStart, 0);
    cudaStreamWaitEvent(s2, evStart, 0);
    convert_all<<<cwh.base[1], dim3(32, 8), 0, s2>>>(cwh);
    cudaEventRecord(evWh, s2);
    convert_all<<<total, dim3(32, 8), 0, s2>>>(crest);
    cudaEventRecord(evRest, s2);

    convert_x<<<dim3(24, 2, 64), dim3(32, 8), 0, 0>>>(x_bsd, xh, xl);
    cudaEventRecord(evX, 0);

    // ---- 3 row-range chains (null, s2, s3) ----
    auto chain = [&](cudaStream_t st, int R, int gx) {
        size_t rx = (size_t)R * 768, rz = (size_t)R * 512;
        size_t ry = (size_t)R * P_, rt = (size_t)R * P2_;
        gemm_mma<EP_GELU><<<dim3(gx, 4), 256, SMEMSZ, st>>>(
            xh + rx, xl + rx, 768, 23, wph + OFF_WH, wpl + OFF_WH, 768, 512,
            ZF, Z, Z, 0, 0.f, ZF, ZF, ZF, hh + rz, hl + rz, nullptr, 512, 0);
        cudaStreamWaitEvent(st, evRest, 0);
        gemm_mma<EP_AFF><<<dim3(gx, 8), 256, SMEMSZ, st>>>(
            hh + rz, hl + rz, 512, 16, wph + OFF_SSZ, wpl + OFF_SSZ, 512, 512,
            z0 + rz, Z, Z, 512, 0.1f, ZF, ZF, ZF, zh + rz, zl + rz, nullptr, 512, 0);
        gemm_mma<EP_AFF><<<dim3(gx, 12), 256, SMEMSZ, st>>>(
            zh + rz, zl + rz, 512, 16, wph + OFF_ZX0, wpl + OFF_ZX0, 512, 720,
            ZF, xh + rx, xl + rx, 768, 1.f, ZF, ZF, ZF, xh + rx, xl + rx, nullptr, 768, 0);
        gemm_mma<EP_AFF><<<dim3(gx, 8), 256, SMEMSZ, st>>>(
            xh + rx, xl + rx, 768, 23, wph + OFF_XZ2, wpl + OFF_XZ2, 768, 512,
            ZF, zh + rz, zl + rz, 512, 1.f, ZF, ZF, ZF, zh + rz, zl + rz, nullptr, 512, 0);
        gemm_mma<EP_AFF><<<dim3(gx, 12), 256, SMEMSZ, st>>>(
            zh + rz, zl + rz, 512, 16, wph + OFF_ZX2, wpl + OFF_ZX2, 512, 720,
            ZF, xh + rx, xl + rx, 768, 1.f, ZF, ZF, ZF, xh + rx, xl + rx, nullptr, 768, 0);
        gemm_mma<EP_AFF><<<dim3(gx, 8), 256, SMEMSZ, st>>>(
            xh + rx, xl + rx, 768, 23, wph + OFF_XZ3, wpl + OFF_XZ3, 768, 512,
            ZF, zh + rz, zl + rz, 512, 1.f, ZF, ZF, ZF, zh + rz, zl + rz, nullptr, 512, 0);
        gemm_mma<EP_AFF><<<dim3(gx, 12), 256, SMEMSZ, st>>>(
            zh + rz, zl + rz, 512, 16, wph + OFF_ZX3, wpl + OFF_ZX3, 512, 720,
            ZF, xh + rx, xl + rx, 768, 1.f, ZF, ZF, ZF, xh + rx, xl + rx, nullptr, 768, 0);
        gemm_mma<EP_AFF><<<dim3(gx, 8), 256, SMEMSZ, st>>>(
            xh + rx, xl + rx, 768, 23, wph + OFF_XZ4, wpl + OFF_XZ4, 768, 512,
            ZF, zh + rz, zl + rz, 512, 1.f, ZF, ZF, ZF, zh + rz, zl + rz, nullptr, 512, 0);
        gemm_mma<EP_AFF><<<dim3(gx, 6), 256, SMEMSZ, st>>>(
            zh + rz, zl + rz, 512, 16, wph + OFF_ZY, wpl + OFF_ZY, 512, 336,
            y0 + ry, Z, Z, 336, 0.1f, ZF, ZF, ZF, nullptr, nullptr, y + ry, 336, 0);
        gemm_mma<EP_AFF><<<dim3(gx, 8), 256, SMEMSZ, st>>>(
            xh + rx, xl + rx, 768, 23, wph + OFF_XZ5, wpl + OFF_XZ5, 768, 512,
            ZF, zh + rz, zl + rz, 512, 1.f, ZF, ZF, ZF, hh + rz, hl + rz, nullptr, 512, 0);
        gemm_mma<EP_TANHPI><<<dim3(gx, 2), 256, SMEMSZ, st>>>(
            hh + rz, hl + rz, 512, 16, wph + OFF_ROT, wpl + OFF_ROT, 512, 168,
            ZF, Z, Z, 0, 0.f, ZF, ZF, ZF, nullptr, nullptr, th + rt, 168, 0);
        gemm_mma<EP_FINAL><<<dim3(gx, 6), 256, SMEMSZ, st>>>(
            hh + rz, hl + rz, 512, 16, wph + OFF_KOO, wpl + OFF_KOO, 512, 336,
            y + ry, Z, Z, 336, 1.f, th + rt, a_y, b_y, nullptr, nullptr, out, 0, R);
    };

    // chain1 on s2 (naturally ordered after both weight converts; wait x)
    cudaStreamWaitEvent(s2, evX, 0);
    chain(s2, CH_R[1], CH_GX[1]);
    cudaEventRecord(evC1, s2);

    // chain2 on s3 (wait x + W_h; evRest waited inside chain)
    cudaStreamWaitEvent(s3, evX, 0);
    cudaStreamWaitEvent(s3, evWh, 0);
    chain(s3, CH_R[2], CH_GX[2]);
    cudaEventRecord(evC2, s3);

    // chain0 on main (convert_x ordered on main; wait W_h)
    cudaStreamWaitEvent(0, evWh, 0);
    chain(nullptr, CH_R[0], CH_GX[0]);

    cudaStreamWaitEvent(0, evC1, 0);
    cudaStreamWaitEvent(0, evC2, 0);
}